// round 15
// baseline (speedup 1.0000x reference)
#include <cuda_runtime.h>
#include <cuda_bf16.h>
#include <mma.h>
#include <cstdint>

// ---------------------------------------------------------------------------
// Arch-feature gate: tcgen05 only legal in sm_103a/sm_100a PTX. The
// compute_103 (no 'a') pass compiles a correct wmma-bf16 fallback.
// ---------------------------------------------------------------------------
#if defined(__CUDA_ARCH__) && \
    (defined(__CUDA_ARCH_FEAT_SM103_ALL) || defined(__CUDA_ARCH_FEAT_SM100_ALL) || \
     (defined(__CUDA_ARCH_SPECIFIC__)        && (__CUDA_ARCH_SPECIFIC__ >= 1000)) || \
     (defined(__CUDA_ARCH_FAMILY_SPECIFIC__) && (__CUDA_ARCH_FAMILY_SPECIFIC__ >= 1000)))
#define HAS_TCGEN05 1
#else
#define HAS_TCGEN05 0
#endif

// ---------------------------------------------------------------------------
// Problem constants
// ---------------------------------------------------------------------------
constexpr int D_MODEL   = 1024;
constexpr int NUM_HEADS = 16;
constexpr int HEAD_DIM  = 64;
constexpr int M_TOK     = 16384;

// 3-term bf16 split: C = a_hi.b_hi + a_lo.b_hi + a_hi.b_lo  (err ~2^-18)
constexpr int KA = 2 * D_MODEL;   // 2048 pack width (acts AND weights)

// GEMM tiling: per CTA 256 M x 256 N (two 128-row MMA subtiles), 16 K-groups.
constexpr int BMC = 256;
constexpr int BN  = 256;
constexpr int NGRP = 16;
constexpr int GEMM_THREADS = 288;  // 8 producer warps + 1 MMA warp

constexpr int TILE_B   = 32768;   // one tile: 256 rows x 128 bytes
constexpr int NSLOT    = 7;       // ring of 7 tiles = 224 KB
constexpr int BAR_OFF    = NSLOT * TILE_B;     // 229376
constexpr int MBARA_OFF  = BAR_OFF;            // 4 x 8B (phase-A commits)
constexpr int MBARF_OFF  = BAR_OFF + 32;       // 4 x 8B (full commits)
constexpr int READY0_OFF = BAR_OFF + 64;       // 4 x 8B (tiles 0-2 landed)
constexpr int READY1_OFF = BAR_OFF + 96;       // 4 x 8B (tile 3 landed)
constexpr int TMEMP_OFF  = BAR_OFF + 128;
constexpr int SMEM_TOTAL = BAR_OFF + 136;      // 229512 <= 232448 cap

constexpr int TMEM_COLS = 512;

// idesc kind::f16 cg1: dtype=F32, a/b=BF16, N=256, M=128
constexpr uint32_t IDESC =
    (1u << 4) | (1u << 7) | (1u << 10) | ((BN / 8) << 17) | ((128 / 16) << 24);

// SW128 K-major smem descriptor base (layout=SW128, version=1, SBO=64, LBO=1)
constexpr uint64_t DESC_BASE_SW128 =
    (uint64_t(2) << 61) | (uint64_t(1) << 46) | (uint64_t(64) << 32) | (uint64_t(1) << 16);

// ---------------------------------------------------------------------------
// Scratch (device globals: allocation-free, graph-capture safe)
// ---------------------------------------------------------------------------
__device__ float          g_Q[M_TOK * D_MODEL];
__device__ float          g_K[M_TOK * D_MODEL];
__device__ float          g_V[M_TOK * D_MODEL];
__device__ __nv_bfloat16  g_a0[(size_t)M_TOK * KA];   // query split / X split
__device__ __nv_bfloat16  g_a1[(size_t)M_TOK * KA];   // key split
__device__ __nv_bfloat16  g_a2[(size_t)M_TOK * KA];   // value split
__device__ __nv_bfloat16  g_w0[(size_t)D_MODEL * KA];
__device__ __nv_bfloat16  g_w1[(size_t)D_MODEL * KA];
__device__ __nv_bfloat16  g_w2[(size_t)D_MODEL * KA];
__device__ __nv_bfloat16  g_w3[(size_t)D_MODEL * KA];

// ---------------------------------------------------------------------------
// Helpers
// ---------------------------------------------------------------------------
__device__ __forceinline__ uint32_t smem_u32(const void* p) {
    return (uint32_t)__cvta_generic_to_shared(p);
}
__device__ __forceinline__ uint32_t elect_one_pred() {
    uint32_t pred;
    asm volatile("{\n\t.reg .pred p;\n\telect.sync _|p, 0xFFFFFFFF;\n\t"
                 "selp.b32 %0, 1, 0, p;\n\t}" : "=r"(pred));
    return pred;
}
#define SWZ128(x) ((x) ^ (((x) >> 3) & 0x70))

#define MBARRIER_INIT(addr, cnt) \
    asm volatile("mbarrier.init.shared.b64 [%0], %1;" :: "r"(addr), "r"((uint32_t)(cnt)) : "memory")
#define MBARRIER_ARRIVE(addr) \
    asm volatile("mbarrier.arrive.shared.b64 _, [%0];" :: "r"(addr) : "memory")

#define MBARRIER_WAIT_PARITY(addr, par) do {                                      \
    uint32_t _m = (addr); uint32_t _p = (par); uint32_t _d;                       \
    asm volatile("{\n\t.reg .pred p;\n\t"                                         \
        "mbarrier.try_wait.parity.acquire.cta.shared::cta.b64 p, [%1], %2;\n\t"   \
        "selp.b32 %0, 1, 0, p;\n\t}" : "=r"(_d) : "r"(_m), "r"(_p) : "memory");   \
    if (!_d) {                                                                    \
        asm volatile("{\n\t.reg .pred P1;\n\t"                                    \
        "WL_%=:\n\t"                                                              \
        "mbarrier.try_wait.parity.acquire.cta.shared::cta.b64 P1, [%0], %1, 0x989680;\n\t" \
        "@P1 bra.uni WD_%=;\n\t"                                                  \
        "bra.uni WL_%=;\n\t"                                                      \
        "WD_%=:\n\t}" :: "r"(_m), "r"(_p) : "memory");                            \
    }                                                                             \
} while (0)

__device__ __forceinline__ void cp_async16(uint32_t dst, const void* src) {
    asm volatile("cp.async.cg.shared.global [%0], [%1], 16;"
                 :: "r"(dst), "l"(src) : "memory");
}

__device__ __forceinline__ void split_row4(float4 v, uint2& hi, uint2& lo) {
    __nv_bfloat162 h01 = __float22bfloat162_rn(make_float2(v.x, v.y));
    __nv_bfloat162 h23 = __float22bfloat162_rn(make_float2(v.z, v.w));
    float2 r01 = make_float2(v.x - __low2float(h01), v.y - __high2float(h01));
    float2 r23 = make_float2(v.z - __low2float(h23), v.w - __high2float(h23));
    __nv_bfloat162 l01 = __float22bfloat162_rn(r01);
    __nv_bfloat162 l23 = __float22bfloat162_rn(r23);
    hi.x = *(uint32_t*)&h01; hi.y = *(uint32_t*)&h23;
    lo.x = *(uint32_t*)&l01; lo.y = *(uint32_t*)&l23;
}

#if HAS_TCGEN05
#define TCGEN05_ALLOC(smem_addr, ncols) \
    asm volatile("tcgen05.alloc.cta_group::1.sync.aligned.shared::cta.b32 [%0], %1;" \
                 :: "r"(smem_addr), "r"((uint32_t)(ncols)) : "memory")
#define TCGEN05_RELINQUISH() \
    asm volatile("tcgen05.relinquish_alloc_permit.cta_group::1.sync.aligned;")
#define TCGEN05_DEALLOC(tmem, ncols) \
    asm volatile("tcgen05.dealloc.cta_group::1.sync.aligned.b32 %0, %1;" \
                 :: "r"(tmem), "r"((uint32_t)(ncols)))
#define TCGEN05_COMMIT(mbar) \
    asm volatile("tcgen05.commit.cta_group::1.mbarrier::arrive::one.shared::cluster.b64 [%0];" \
                 :: "r"(mbar) : "memory")
#define TCGEN05_FENCE_AFTER() \
    asm volatile("tcgen05.fence::after_thread_sync;" ::: "memory")
#define TCGEN05_WAIT_LD() \
    asm volatile("tcgen05.wait::ld.sync.aligned;" ::: "memory")
#define FENCE_PROXY_ASYNC() \
    asm volatile("fence.proxy.async.shared::cta;" ::: "memory")

#define TCGEN05_LD_X32(r, addr)                                              \
    asm volatile("tcgen05.ld.sync.aligned.32x32b.x32.b32 "                   \
        "{%0, %1, %2, %3, %4, %5, %6, %7, "                                  \
        " %8, %9, %10, %11, %12, %13, %14, %15, "                            \
        " %16, %17, %18, %19, %20, %21, %22, %23, "                          \
        " %24, %25, %26, %27, %28, %29, %30, %31}, [%32];"                   \
        : "=r"((r)[0]),  "=r"((r)[1]),  "=r"((r)[2]),  "=r"((r)[3]),         \
          "=r"((r)[4]),  "=r"((r)[5]),  "=r"((r)[6]),  "=r"((r)[7]),         \
          "=r"((r)[8]),  "=r"((r)[9]),  "=r"((r)[10]), "=r"((r)[11]),        \
          "=r"((r)[12]), "=r"((r)[13]), "=r"((r)[14]), "=r"((r)[15]),        \
          "=r"((r)[16]), "=r"((r)[17]), "=r"((r)[18]), "=r"((r)[19]),        \
          "=r"((r)[20]), "=r"((r)[21]), "=r"((r)[22]), "=r"((r)[23]),        \
          "=r"((r)[24]), "=r"((r)[25]), "=r"((r)[26]), "=r"((r)[27]),        \
          "=r"((r)[28]), "=r"((r)[29]), "=r"((r)[30]), "=r"((r)[31])         \
        : "r"(addr))

__device__ __forceinline__ void mma_f16_ss_cg1(uint32_t d_tmem, uint64_t adesc,
                                               uint64_t bdesc, uint32_t idesc,
                                               uint32_t enable) {
    asm volatile(
        "{\n\t.reg .pred p;\n\tsetp.ne.u32 p, %4, 0;\n\t"
        "tcgen05.mma.cta_group::1.kind::f16 [%0], %1, %2, %3, {%5,%5,%5,%5}, p;\n\t}"
        :: "r"(d_tmem), "l"(adesc), "l"(bdesc), "r"(idesc), "r"(enable), "r"(0u)
        : "memory");
}

// Tile j: group g=j>>2, class j&3: 0=B_hi, 1=A_lo, 2=A_hi, 3=B_lo.
// A tiles: 256 rows x 64 bf16 as two 128-row subtiles (+0 / +16KB).
__device__ __forceinline__ void copy_tile(int j, int tid, uint32_t sbase,
                                          const __nv_bfloat16* A,
                                          const __nv_bfloat16* B,
                                          int m0, int n0) {
    const int g = j >> 2, cls = j & 3;
    const uint32_t base = sbase + (uint32_t)(j % NSLOT) * TILE_B;
    const bool isA = (cls == 1) || (cls == 2);
    const int off = ((cls == 1) || (cls == 3)) ? (2048 + g * 128) : (g * 128);
    const char* src = isA ? ((const char*)A + (size_t)m0 * 4096 + off)
                          : ((const char*)B + (size_t)n0 * 4096 + off);
#pragma unroll
    for (int p = 0; p < 8; p++) {
        int u = tid + p * 256;
        int r = u >> 3, c = u & 7;
        uint32_t dst = isA
            ? (base + (uint32_t)((r >> 7) * 16384) + SWZ128((r & 127) * 128 + c * 16))
            : (base + SWZ128(r * 128 + c * 16));
        cp_async16(dst, src + (size_t)r * 4096 + c * 16);
    }
}
#endif  // HAS_TCGEN05

// ---------------------------------------------------------------------------
// GEMM core (warp-specialized, split-ready pipeline, overlapped prologue)
// ---------------------------------------------------------------------------
__device__ __forceinline__ void gemm_core(const __nv_bfloat16* __restrict__ A,
                                          const __nv_bfloat16* __restrict__ B,
                                          const float* __restrict__ bias,
                                          float* __restrict__ C,
                                          char* smem)
{
    const int tid = threadIdx.x;
    const int m0 = blockIdx.y * BMC;
    const int n0 = blockIdx.x * BN;

#if HAS_TCGEN05
    const uint32_t sbase = smem_u32(smem);

    if (tid < 256) {
        // Producers: start group-0 copies immediately (no barrier/TMEM dep).
        copy_tile(0, tid, sbase, A, B, m0, n0);
        copy_tile(1, tid, sbase, A, B, m0, n0);
        copy_tile(2, tid, sbase, A, B, m0, n0);
        asm volatile("cp.async.commit_group;" ::: "memory");
        copy_tile(3, tid, sbase, A, B, m0, n0);
        asm volatile("cp.async.commit_group;" ::: "memory");
    } else {
        // MMA warp: init barriers + TMEM alloc, overlapped with copies.
        if (elect_one_pred()) {
#pragma unroll
            for (int s = 0; s < 4; s++) {
                MBARRIER_INIT(sbase + MBARA_OFF + s * 8, 1);
                MBARRIER_INIT(sbase + MBARF_OFF + s * 8, 1);
                MBARRIER_INIT(sbase + READY0_OFF + s * 8, 256);
                MBARRIER_INIT(sbase + READY1_OFF + s * 8, 256);
            }
        }
        TCGEN05_ALLOC(sbase + TMEMP_OFF, TMEM_COLS);
        TCGEN05_RELINQUISH();
    }
    __syncthreads();
    uint32_t tmem;
    asm volatile("ld.shared.b32 %0, [%1];" : "=r"(tmem) : "r"(sbase + TMEMP_OFF));

    if (tid < 256) {
        // ======================= producer warps ==========================
        for (int g = 0; g < NGRP; g++) {
            // pending cp.async groups at this point: {A_g, B_g}
            asm volatile("cp.async.wait_group 1;" ::: "memory");   // A_g landed
            MBARRIER_ARRIVE(sbase + READY0_OFF + (g & 3) * 8);
            asm volatile("cp.async.wait_group 0;" ::: "memory");   // B_g landed
            MBARRIER_ARRIVE(sbase + READY1_OFF + (g & 3) * 8);

            if (g + 1 < NGRP) {
                // tiles 4g+4..6 : slots freed by MBARA(g-1), MBARF(g-1)
                if (g >= 1) {
                    MBARRIER_WAIT_PARITY(sbase + MBARA_OFF + ((g - 1) & 3) * 8,
                                         (uint32_t)(((g - 1) >> 2) & 1));
                }
                copy_tile(4 * g + 4, tid, sbase, A, B, m0, n0);
                if (g >= 1) {
                    MBARRIER_WAIT_PARITY(sbase + MBARF_OFF + ((g - 1) & 3) * 8,
                                         (uint32_t)(((g - 1) >> 2) & 1));
                }
                copy_tile(4 * g + 5, tid, sbase, A, B, m0, n0);
                copy_tile(4 * g + 6, tid, sbase, A, B, m0, n0);
                asm volatile("cp.async.commit_group;" ::: "memory");  // A_{g+1}
                // tile 4g+7 : slot freed by MBARA(g) (fires mid-MMA(g))
                MBARRIER_WAIT_PARITY(sbase + MBARA_OFF + (g & 3) * 8,
                                     (uint32_t)((g >> 2) & 1));
                copy_tile(4 * g + 7, tid, sbase, A, B, m0, n0);
                asm volatile("cp.async.commit_group;" ::: "memory");  // B_{g+1}
            }
        }

        // ======================= epilogue (producers) =====================
        MBARRIER_WAIT_PARITY(sbase + MBARF_OFF + ((NGRP - 1) & 3) * 8,
                             (uint32_t)(((NGRP - 1) >> 2) & 1));
        TCGEN05_FENCE_AFTER();
        {
            const int w = tid >> 5, lid = tid & 31;
            const int half = w >> 2;
            const int row  = (w & 3) * 32 + lid;
            const uint32_t dbase = tmem + half * 256;
            float* crow = C + (size_t)(m0 + half * 128 + row) * D_MODEL + n0;
#pragma unroll
            for (int cc = 0; cc < 8; cc += 2) {   // 2 LDTMs in flight per wait
                const int col0 = cc * 32;
                uint32_t d0[32], d1[32];
                TCGEN05_LD_X32(d0, dbase + col0);
                TCGEN05_LD_X32(d1, dbase + col0 + 32);
                TCGEN05_WAIT_LD();
#pragma unroll
                for (int j = 0; j < 32; j += 4) {
                    float4 bv = *(const float4*)(bias + n0 + col0 + j);
                    float4 v;
                    v.x = __uint_as_float(d0[j + 0]) + bv.x;
                    v.y = __uint_as_float(d0[j + 1]) + bv.y;
                    v.z = __uint_as_float(d0[j + 2]) + bv.z;
                    v.w = __uint_as_float(d0[j + 3]) + bv.w;
                    *(float4*)(crow + col0 + j) = v;
                }
#pragma unroll
                for (int j = 0; j < 32; j += 4) {
                    float4 bv = *(const float4*)(bias + n0 + col0 + 32 + j);
                    float4 v;
                    v.x = __uint_as_float(d1[j + 0]) + bv.x;
                    v.y = __uint_as_float(d1[j + 1]) + bv.y;
                    v.z = __uint_as_float(d1[j + 2]) + bv.z;
                    v.w = __uint_as_float(d1[j + 3]) + bv.w;
                    *(float4*)(crow + col0 + 32 + j) = v;
                }
            }
        }
    } else {
        // ========================= MMA warp ===============================
        // READY0 wait at top; READY1 wait only before phase 3 (B_lo arrival
        // latency hidden behind phases 1-2).
        if (elect_one_pred()) {
            for (int g = 0; g < NGRP; g++) {
                const uint32_t par = (uint32_t)((g >> 2) & 1);
                MBARRIER_WAIT_PARITY(sbase + READY0_OFF + (g & 3) * 8, par);
                FENCE_PROXY_ASYNC();
                const uint64_t dBhi = DESC_BASE_SW128 |
                    (((uint64_t)((sbase + (uint32_t)(((4 * g + 0) % NSLOT) * TILE_B)) >> 4)) & 0x3FFF);
                const uint64_t dAlo = DESC_BASE_SW128 |
                    (((uint64_t)((sbase + (uint32_t)(((4 * g + 1) % NSLOT) * TILE_B)) >> 4)) & 0x3FFF);
                const uint64_t dAhi = DESC_BASE_SW128 |
                    (((uint64_t)((sbase + (uint32_t)(((4 * g + 2) % NSLOT) * TILE_B)) >> 4)) & 0x3FFF);
                const uint64_t dBlo = DESC_BASE_SW128 |
                    (((uint64_t)((sbase + (uint32_t)(((4 * g + 3) % NSLOT) * TILE_B)) >> 4)) & 0x3FFF);

                // phase 1: a_hi . b_hi
#pragma unroll
                for (int q = 0; q < 4; q++) {
                    uint32_t en = (uint32_t)((g > 0) || (q > 0));
                    mma_f16_ss_cg1(tmem,       dAhi + 2 * q,        dBhi + 2 * q, IDESC, en);
                    mma_f16_ss_cg1(tmem + 256, dAhi + 1024 + 2 * q, dBhi + 2 * q, IDESC, en);
                }
                // phase 2: a_lo . b_hi
#pragma unroll
                for (int q = 0; q < 4; q++) {
                    mma_f16_ss_cg1(tmem,       dAlo + 2 * q,        dBhi + 2 * q, IDESC, 1);
                    mma_f16_ss_cg1(tmem + 256, dAlo + 1024 + 2 * q, dBhi + 2 * q, IDESC, 1);
                }
                TCGEN05_COMMIT(sbase + MBARA_OFF + (g & 3) * 8);   // frees B_hi, A_lo
                // phase 3: a_hi . b_lo  (needs tile 3)
                MBARRIER_WAIT_PARITY(sbase + READY1_OFF + (g & 3) * 8, par);
                FENCE_PROXY_ASYNC();
#pragma unroll
                for (int q = 0; q < 4; q++) {
                    mma_f16_ss_cg1(tmem,       dAhi + 2 * q,        dBlo + 2 * q, IDESC, 1);
                    mma_f16_ss_cg1(tmem + 256, dAhi + 1024 + 2 * q, dBlo + 2 * q, IDESC, 1);
                }
                TCGEN05_COMMIT(sbase + MBARF_OFF + (g & 3) * 8);   // frees A_hi, B_lo
            }
        }
    }

    __syncthreads();
    if (tid < 32) TCGEN05_DEALLOC(tmem, TMEM_COLS);

#else
    // ================== wmma bf16 fallback (plain sm_103) =================
    using namespace nvcuda;
    using FA = wmma::fragment<wmma::matrix_a, 16, 16, 16, __nv_bfloat16, wmma::row_major>;
    using FB = wmma::fragment<wmma::matrix_b, 16, 16, 16, __nv_bfloat16, wmma::col_major>;
    using FC = wmma::fragment<wmma::accumulator, 16, 16, 16, float>;

    constexpr int BKF  = 32;
    constexpr int LDF  = BKF + 8;
    constexpr int LDCF = 128 + 4;

    __nv_bfloat16* As = (__nv_bfloat16*)smem;
    __nv_bfloat16* Bs = As + 128 * LDF;
    float*         Cs = (float*)smem;

    const int warp = tid >> 5;
    const int wm = warp >> 1;
    const int wn = warp & 1;
    const bool active = (tid < 256);

    for (int mt = 0; mt < 2; mt++) {
        const int m0h = m0 + mt * 128;
        for (int half = 0; half < 2; half++) {
            const int n0h = n0 + half * 128;
            FC acc[2][4];
#pragma unroll
            for (int a = 0; a < 2; a++)
#pragma unroll
                for (int b = 0; b < 4; b++) wmma::fill_fragment(acc[a][b], 0.0f);

            for (int term = 0; term < 3; term++) {
                const int aoff = (term == 1) ? 1024 : 0;
                const int boff = (term == 2) ? 1024 : 0;
                for (int kt = 0; kt < 1024; kt += BKF) {
                    if (active) {
#pragma unroll
                        for (int p = 0; p < 2; p++) {
                            int idx = tid + p * 256;
                            int r = idx >> 2, cidx = idx & 3;
                            *(uint4*)(As + r * LDF + cidx * 8) =
                                *(const uint4*)(A + (size_t)(m0h + r) * KA + aoff + kt + cidx * 8);
                            *(uint4*)(Bs + r * LDF + cidx * 8) =
                                *(const uint4*)(B + (size_t)(n0h + r) * KA + boff + kt + cidx * 8);
                        }
                    }
                    __syncthreads();
                    if (active) {
#pragma unroll
                        for (int kk = 0; kk < BKF; kk += 16) {
                            FA af[2];
                            FB bf[4];
#pragma unroll
                            for (int mi = 0; mi < 2; mi++)
                                wmma::load_matrix_sync(af[mi], As + (wm * 32 + mi * 16) * LDF + kk, LDF);
#pragma unroll
                            for (int ni = 0; ni < 4; ni++)
                                wmma::load_matrix_sync(bf[ni], Bs + (wn * 64 + ni * 16) * LDF + kk, LDF);
#pragma unroll
                            for (int mi = 0; mi < 2; mi++)
#pragma unroll
                                for (int ni = 0; ni < 4; ni++)
                                    wmma::mma_sync(acc[mi][ni], af[mi], bf[ni], acc[mi][ni]);
                        }
                    }
                    __syncthreads();
                }
            }

            if (active) {
#pragma unroll
                for (int mi = 0; mi < 2; mi++)
#pragma unroll
                    for (int ni = 0; ni < 4; ni++)
                        wmma::store_matrix_sync(Cs + (wm * 32 + mi * 16) * LDCF + wn * 64 + ni * 16,
                                                acc[mi][ni], LDCF, wmma::mem_row_major);
            }
            __syncthreads();

            if (active) {
                const int c4 = tid & 31;
                const int r0 = tid >> 5;
                float4 bv = *(const float4*)(bias + n0h + c4 * 4);
#pragma unroll
                for (int rr = 0; rr < 128; rr += 8) {
                    int r = rr + r0;
                    float4 v = *(float4*)(Cs + r * LDCF + c4 * 4);
                    v.x += bv.x; v.y += bv.y; v.z += bv.z; v.w += bv.w;
                    *(float4*)(C + (size_t)(m0h + r) * D_MODEL + n0h + c4 * 4) = v;
                }
            }
            __syncthreads();
        }
    }
#endif
}

// Fused QKV GEMM. grid (4,64,3), 288 threads
__global__ void __launch_bounds__(GEMM_THREADS, 1)
gemm_qkv(const __nv_bfloat16* __restrict__ a0, const __nv_bfloat16* __restrict__ a1,
         const __nv_bfloat16* __restrict__ a2,
         const __nv_bfloat16* __restrict__ w0, const __nv_bfloat16* __restrict__ w1,
         const __nv_bfloat16* __restrict__ w2,
         const float* __restrict__ bq, const float* __restrict__ bk,
         const float* __restrict__ bv,
         float* __restrict__ cq, float* __restrict__ ck, float* __restrict__ cv)
{
    extern __shared__ __align__(1024) char smem[];
    const int z = blockIdx.z;
    const __nv_bfloat16* A = (z == 0) ? a0 : (z == 1) ? a1 : a2;
    const __nv_bfloat16* W = (z == 0) ? w0 : (z == 1) ? w1 : w2;
    const float* bias      = (z == 0) ? bq : (z == 1) ? bk : bv;
    float* C               = (z == 0) ? cq : (z == 1) ? ck : cv;
    gemm_core(A, W, bias, C, smem);
}

// Single GEMM (output projection). grid (4,64), 288 threads
__global__ void __launch_bounds__(GEMM_THREADS, 1)
gemm_one(const __nv_bfloat16* __restrict__ A, const __nv_bfloat16* __restrict__ W,
         const float* __restrict__ bias, float* __restrict__ C)
{
    extern __shared__ __align__(1024) char smem[];
    gemm_core(A, W, bias, C, smem);
}

// ---------------------------------------------------------------------------
// Fused split: weights (blocks 0..4095) + activations (blocks 4096..53247)
// fp32 -> [hi|lo] bf16, width 2048. One launch.
// ---------------------------------------------------------------------------
__global__ void __launch_bounds__(256)
split_all(const float* __restrict__ w0, const float* __restrict__ w1,
          const float* __restrict__ w2, const float* __restrict__ w3,
          __nv_bfloat16* __restrict__ o0, __nv_bfloat16* __restrict__ o1,
          __nv_bfloat16* __restrict__ o2, __nv_bfloat16* __restrict__ o3,
          const float* __restrict__ q, const float* __restrict__ k,
          const float* __restrict__ v,
          __nv_bfloat16* __restrict__ oq, __nv_bfloat16* __restrict__ ok,
          __nv_bfloat16* __restrict__ ov)
{
    const int b = blockIdx.x;
    const float* in;
    __nv_bfloat16* out;
    size_t row;
    if (b < 4096) {                       // weights
        const int which = b >> 10;
        row = (size_t)(b & 1023);
        in  = (which == 0) ? w0 : (which == 1) ? w1 : (which == 2) ? w2 : w3;
        out = (which == 0) ? o0 : (which == 1) ? o1 : (which == 2) ? o2 : o3;
    } else {                              // activations
        const int idx = b - 4096;
        const int which = idx >> 14;
        row = (size_t)(idx & 16383);
        in  = (which == 0) ? q : (which == 1) ? k : v;
        out = (which == 0) ? oq : (which == 1) ? ok : ov;
    }

    const int col = threadIdx.x * 4;
    uint2 hi, lo;
    split_row4(*(const float4*)(in + row * D_MODEL + col), hi, lo);
    *(uint2*)(out + row * KA + col)           = hi;
    *(uint2*)(out + row * KA + D_MODEL + col) = lo;
}

// ---------------------------------------------------------------------------
// Per-token "attention" mix; writes X directly as [hi|lo] bf16 split.
// A@V remapped: each thread computes 4 consecutive od for one oi ->
// vs reads become LDS.128, a_s reads become warp broadcasts, stores vectorize.
// ---------------------------------------------------------------------------
__global__ void __launch_bounds__(256)
attn_mix_split(const float* __restrict__ Q,
               const float* __restrict__ K,
               const float* __restrict__ V,
               const int*   __restrict__ mask,
               __nv_bfloat16* __restrict__ Xs)
{
    __shared__ __align__(16) float qs[D_MODEL];
    __shared__ __align__(16) float vs[D_MODEL];
    __shared__ __align__(16) float kT[D_MODEL];
    __shared__ float a_s[NUM_HEADS * NUM_HEADS];

    const int t = threadIdx.x;
    const size_t base = (size_t)blockIdx.x * D_MODEL;

    float4 q4 = *(const float4*)(Q + base + t * 4);
    float4 v4 = *(const float4*)(V + base + t * 4);
    float4 k4 = *(const float4*)(K + base + t * 4);
    *(float4*)(qs + t * 4) = q4;
    *(float4*)(vs + t * 4) = v4;
    {   // vectorized swizzled transpose: 4 consecutive d share l and d>>2
        int j = t * 4;
        int d0 = j & 63, l0 = j >> 6;
        int x = l0 ^ (d0 >> 2);
        *(float4*)(kT + (d0 >> 2) * 64 + x * 4) = k4;
    }
    __syncthreads();

    const int i = t >> 4, l = t & 15;
    float e = 0.0f;
#pragma unroll
    for (int d = 0; d < HEAD_DIM; d += 4) {
        float4 qv = *(const float4*)(qs + i * 64 + d);
        float4 kv = *(const float4*)(kT + (d >> 2) * 64 + (l ^ (d >> 2)) * 4);
        e += qv.x * kv.x + qv.y * kv.y + qv.z * kv.z + qv.w * kv.w;
    }

    const int mk = mask[blockIdx.x];
    e = mk ? e * 0.03125f : 0.0f;         // 1/sqrt(1024); masked -> uniform

    float mx = e;
#pragma unroll
    for (int off = 8; off; off >>= 1)
        mx = fmaxf(mx, __shfl_xor_sync(0xffffffffu, mx, off, 16));
    float p = expf(e - mx);
    float s = p;
#pragma unroll
    for (int off = 8; off; off >>= 1)
        s += __shfl_xor_sync(0xffffffffu, s, off, 16);
    a_s[t] = p / s;
    __syncthreads();

    // X = A @ V_heads: thread -> (oi = t>>4, od = (t&15)*4 .. +3)
    const int oi  = t >> 4;
    const int od0 = (t & 15) * 4;
    float4 acc = make_float4(0.f, 0.f, 0.f, 0.f);
#pragma unroll
    for (int ll = 0; ll < 16; ll++) {
        float a = a_s[oi * 16 + ll];                       // warp broadcast
        float4 vv = *(const float4*)(vs + ll * 64 + od0);  // LDS.128
        acc.x += a * vv.x;
        acc.y += a * vv.y;
        acc.z += a * vv.z;
        acc.w += a * vv.w;
    }
    // write [hi|lo] bf16 split, vectorized (8B hi + 8B lo)
    const size_t obase = (size_t)blockIdx.x * KA;
    const int o = oi * 64 + od0;
    uint2 hi, lo;
    split_row4(acc, hi, lo);
    *(uint2*)(Xs + obase + o)           = hi;
    *(uint2*)(Xs + obase + D_MODEL + o) = lo;
}

// ---------------------------------------------------------------------------
// Launch
// ---------------------------------------------------------------------------
extern "C" void kernel_launch(void* const* d_in, const int* in_sizes, int n_in,
                              void* d_out, int out_size)
{
    (void)in_sizes; (void)n_in; (void)out_size;
    const float* query = (const float*)d_in[0];
    const float* key   = (const float*)d_in[1];
    const float* value = (const float*)d_in[2];
    const int*   mask  = (const int*)  d_in[3];
    const float* Wq = (const float*)d_in[4];
    const float* bq = (const float*)d_in[5];
    const float* Wk = (const float*)d_in[6];
    const float* bk = (const float*)d_in[7];
    const float* Wv = (const float*)d_in[8];
    const float* bv = (const float*)d_in[9];
    const float* Wo = (const float*)d_in[10];
    const float* bo = (const float*)d_in[11];
    float* out = (float*)d_out;

    void *pQ, *pK, *pV, *pA0, *pA1, *pA2, *pW0, *pW1, *pW2, *pW3;
    cudaGetSymbolAddress(&pQ, g_Q);
    cudaGetSymbolAddress(&pK, g_K);
    cudaGetSymbolAddress(&pV, g_V);
    cudaGetSymbolAddress(&pA0, g_a0);
    cudaGetSymbolAddress(&pA1, g_a1);
    cudaGetSymbolAddress(&pA2, g_a2);
    cudaGetSymbolAddress(&pW0, g_w0);
    cudaGetSymbolAddress(&pW1, g_w1);
    cudaGetSymbolAddress(&pW2, g_w2);
    cudaGetSymbolAddress(&pW3, g_w3);

    cudaFuncSetAttribute(gemm_qkv,
                         cudaFuncAttributeMaxDynamicSharedMemorySize, SMEM_TOTAL);
    cudaFuncSetAttribute(gemm_one,
                         cudaFuncAttributeMaxDynamicSharedMemorySize, SMEM_TOTAL);

    split_all<<<4096 + 3 * M_TOK, 256>>>(
        Wq, Wk, Wv, Wo,
        (__nv_bfloat16*)pW0, (__nv_bfloat16*)pW1,
        (__nv_bfloat16*)pW2, (__nv_bfloat16*)pW3,
        query, key, value,
        (__nv_bfloat16*)pA0, (__nv_bfloat16*)pA1, (__nv_bfloat16*)pA2);

    dim3 qkvgrid(D_MODEL / BN, M_TOK / BMC, 3);   // (4, 64, 3)
    gemm_qkv<<<qkvgrid, GEMM_THREADS, SMEM_TOTAL>>>(
        (__nv_bfloat16*)pA0, (__nv_bfloat16*)pA1, (__nv_bfloat16*)pA2,
        (__nv_bfloat16*)pW0, (__nv_bfloat16*)pW1, (__nv_bfloat16*)pW2,
        bq, bk, bv, (float*)pQ, (float*)pK, (float*)pV);

    attn_mix_split<<<M_TOK, 256>>>((const float*)pQ, (const float*)pK,
                                   (const float*)pV, mask, (__nv_bfloat16*)pA0);

    dim3 ogrid(D_MODEL / BN, M_TOK / BMC);        // (4, 64)
    gemm_one<<<ogrid, GEMM_THREADS, SMEM_TOTAL>>>((__nv_bfloat16*)pA0,
                                                  (__nv_bfloat16*)pW3, bo, out);
}

// round 16
// speedup vs baseline: 1.0252x; 1.0252x over previous
#include <cuda_runtime.h>
#include <cuda_bf16.h>
#include <mma.h>
#include <cstdint>

// ---------------------------------------------------------------------------
// Arch-feature gate: tcgen05 only legal in sm_103a/sm_100a PTX. The
// compute_103 (no 'a') pass compiles a correct wmma-bf16 fallback.
// ---------------------------------------------------------------------------
#if defined(__CUDA_ARCH__) && \
    (defined(__CUDA_ARCH_FEAT_SM103_ALL) || defined(__CUDA_ARCH_FEAT_SM100_ALL) || \
     (defined(__CUDA_ARCH_SPECIFIC__)        && (__CUDA_ARCH_SPECIFIC__ >= 1000)) || \
     (defined(__CUDA_ARCH_FAMILY_SPECIFIC__) && (__CUDA_ARCH_FAMILY_SPECIFIC__ >= 1000)))
#define HAS_TCGEN05 1
#else
#define HAS_TCGEN05 0
#endif

// ---------------------------------------------------------------------------
// Problem constants
// ---------------------------------------------------------------------------
constexpr int D_MODEL   = 1024;
constexpr int NUM_HEADS = 16;
constexpr int HEAD_DIM  = 64;
constexpr int M_TOK     = 16384;

// 3-term bf16 split: C = a_hi.b_hi + a_lo.b_hi + a_hi.b_lo  (err ~2^-18)
constexpr int KA = 2 * D_MODEL;   // 2048 pack width (acts AND weights)

// GEMM tiling: per CTA 256 M x 256 N (two 128-row MMA subtiles), 16 K-groups.
constexpr int BMC = 256;
constexpr int BN  = 256;
constexpr int NGRP = 16;
constexpr int GEMM_THREADS = 288;  // 8 producer warps + 1 MMA warp

constexpr int TILE_B   = 32768;   // one tile: 256 rows x 128 bytes
constexpr int NSLOT    = 7;       // ring of 7 tiles = 224 KB
constexpr int BAR_OFF    = NSLOT * TILE_B;     // 229376
constexpr int MBARA_OFF  = BAR_OFF;            // 4 x 8B (phase-A commits)
constexpr int MBARF_OFF  = BAR_OFF + 32;       // 4 x 8B (full commits)
constexpr int READY0_OFF = BAR_OFF + 64;       // 4 x 8B (tiles 0-2 landed)
constexpr int READY1_OFF = BAR_OFF + 96;       // 4 x 8B (tile 3 landed)
constexpr int TMEMP_OFF  = BAR_OFF + 128;
constexpr int SMEM_TOTAL = BAR_OFF + 136;      // 229512 <= 232448 cap

constexpr int TMEM_COLS = 512;

// idesc kind::f16 cg1: dtype=F32, a/b=BF16, N=256, M=128
constexpr uint32_t IDESC =
    (1u << 4) | (1u << 7) | (1u << 10) | ((BN / 8) << 17) | ((128 / 16) << 24);

// SW128 K-major smem descriptor base (layout=SW128, version=1, SBO=64, LBO=1)
constexpr uint64_t DESC_BASE_SW128 =
    (uint64_t(2) << 61) | (uint64_t(1) << 46) | (uint64_t(64) << 32) | (uint64_t(1) << 16);

// ---------------------------------------------------------------------------
// Scratch (device globals: allocation-free, graph-capture safe)
// ---------------------------------------------------------------------------
__device__ float          g_Q[M_TOK * D_MODEL];
__device__ float          g_K[M_TOK * D_MODEL];
__device__ float          g_V[M_TOK * D_MODEL];
__device__ __nv_bfloat16  g_a0[(size_t)M_TOK * KA];   // query split / X split
__device__ __nv_bfloat16  g_a1[(size_t)M_TOK * KA];   // key split
__device__ __nv_bfloat16  g_a2[(size_t)M_TOK * KA];   // value split
__device__ __nv_bfloat16  g_w0[(size_t)D_MODEL * KA];
__device__ __nv_bfloat16  g_w1[(size_t)D_MODEL * KA];
__device__ __nv_bfloat16  g_w2[(size_t)D_MODEL * KA];
__device__ __nv_bfloat16  g_w3[(size_t)D_MODEL * KA];

// ---------------------------------------------------------------------------
// Helpers
// ---------------------------------------------------------------------------
__device__ __forceinline__ uint32_t smem_u32(const void* p) {
    return (uint32_t)__cvta_generic_to_shared(p);
}
__device__ __forceinline__ uint32_t elect_one_pred() {
    uint32_t pred;
    asm volatile("{\n\t.reg .pred p;\n\telect.sync _|p, 0xFFFFFFFF;\n\t"
                 "selp.b32 %0, 1, 0, p;\n\t}" : "=r"(pred));
    return pred;
}
#define SWZ128(x) ((x) ^ (((x) >> 3) & 0x70))

#define MBARRIER_INIT(addr, cnt) \
    asm volatile("mbarrier.init.shared.b64 [%0], %1;" :: "r"(addr), "r"((uint32_t)(cnt)) : "memory")
#define MBARRIER_ARRIVE(addr) \
    asm volatile("mbarrier.arrive.shared.b64 _, [%0];" :: "r"(addr) : "memory")

#define MBARRIER_WAIT_PARITY(addr, par) do {                                      \
    uint32_t _m = (addr); uint32_t _p = (par); uint32_t _d;                       \
    asm volatile("{\n\t.reg .pred p;\n\t"                                         \
        "mbarrier.try_wait.parity.acquire.cta.shared::cta.b64 p, [%1], %2;\n\t"   \
        "selp.b32 %0, 1, 0, p;\n\t}" : "=r"(_d) : "r"(_m), "r"(_p) : "memory");   \
    if (!_d) {                                                                    \
        asm volatile("{\n\t.reg .pred P1;\n\t"                                    \
        "WL_%=:\n\t"                                                              \
        "mbarrier.try_wait.parity.acquire.cta.shared::cta.b64 P1, [%0], %1, 0x989680;\n\t" \
        "@P1 bra.uni WD_%=;\n\t"                                                  \
        "bra.uni WL_%=;\n\t"                                                      \
        "WD_%=:\n\t}" :: "r"(_m), "r"(_p) : "memory");                            \
    }                                                                             \
} while (0)

__device__ __forceinline__ void cp_async16(uint32_t dst, const void* src) {
    asm volatile("cp.async.cg.shared.global [%0], [%1], 16;"
                 :: "r"(dst), "l"(src) : "memory");
}

__device__ __forceinline__ void split_row4(float4 v, uint2& hi, uint2& lo) {
    __nv_bfloat162 h01 = __float22bfloat162_rn(make_float2(v.x, v.y));
    __nv_bfloat162 h23 = __float22bfloat162_rn(make_float2(v.z, v.w));
    float2 r01 = make_float2(v.x - __low2float(h01), v.y - __high2float(h01));
    float2 r23 = make_float2(v.z - __low2float(h23), v.w - __high2float(h23));
    __nv_bfloat162 l01 = __float22bfloat162_rn(r01);
    __nv_bfloat162 l23 = __float22bfloat162_rn(r23);
    hi.x = *(uint32_t*)&h01; hi.y = *(uint32_t*)&h23;
    lo.x = *(uint32_t*)&l01; lo.y = *(uint32_t*)&l23;
}

#if HAS_TCGEN05
#define TCGEN05_ALLOC(smem_addr, ncols) \
    asm volatile("tcgen05.alloc.cta_group::1.sync.aligned.shared::cta.b32 [%0], %1;" \
                 :: "r"(smem_addr), "r"((uint32_t)(ncols)) : "memory")
#define TCGEN05_RELINQUISH() \
    asm volatile("tcgen05.relinquish_alloc_permit.cta_group::1.sync.aligned;")
#define TCGEN05_DEALLOC(tmem, ncols) \
    asm volatile("tcgen05.dealloc.cta_group::1.sync.aligned.b32 %0, %1;" \
                 :: "r"(tmem), "r"((uint32_t)(ncols)))
#define TCGEN05_COMMIT(mbar) \
    asm volatile("tcgen05.commit.cta_group::1.mbarrier::arrive::one.shared::cluster.b64 [%0];" \
                 :: "r"(mbar) : "memory")
#define TCGEN05_FENCE_AFTER() \
    asm volatile("tcgen05.fence::after_thread_sync;" ::: "memory")
#define TCGEN05_WAIT_LD() \
    asm volatile("tcgen05.wait::ld.sync.aligned;" ::: "memory")
#define FENCE_PROXY_ASYNC() \
    asm volatile("fence.proxy.async.shared::cta;" ::: "memory")

#define TCGEN05_LD_X32(r, addr)                                              \
    asm volatile("tcgen05.ld.sync.aligned.32x32b.x32.b32 "                   \
        "{%0, %1, %2, %3, %4, %5, %6, %7, "                                  \
        " %8, %9, %10, %11, %12, %13, %14, %15, "                            \
        " %16, %17, %18, %19, %20, %21, %22, %23, "                          \
        " %24, %25, %26, %27, %28, %29, %30, %31}, [%32];"                   \
        : "=r"((r)[0]),  "=r"((r)[1]),  "=r"((r)[2]),  "=r"((r)[3]),         \
          "=r"((r)[4]),  "=r"((r)[5]),  "=r"((r)[6]),  "=r"((r)[7]),         \
          "=r"((r)[8]),  "=r"((r)[9]),  "=r"((r)[10]), "=r"((r)[11]),        \
          "=r"((r)[12]), "=r"((r)[13]), "=r"((r)[14]), "=r"((r)[15]),        \
          "=r"((r)[16]), "=r"((r)[17]), "=r"((r)[18]), "=r"((r)[19]),        \
          "=r"((r)[20]), "=r"((r)[21]), "=r"((r)[22]), "=r"((r)[23]),        \
          "=r"((r)[24]), "=r"((r)[25]), "=r"((r)[26]), "=r"((r)[27]),        \
          "=r"((r)[28]), "=r"((r)[29]), "=r"((r)[30]), "=r"((r)[31])         \
        : "r"(addr))

__device__ __forceinline__ void mma_f16_ss_cg1(uint32_t d_tmem, uint64_t adesc,
                                               uint64_t bdesc, uint32_t idesc,
                                               uint32_t enable) {
    asm volatile(
        "{\n\t.reg .pred p;\n\tsetp.ne.u32 p, %4, 0;\n\t"
        "tcgen05.mma.cta_group::1.kind::f16 [%0], %1, %2, %3, {%5,%5,%5,%5}, p;\n\t}"
        :: "r"(d_tmem), "l"(adesc), "l"(bdesc), "r"(idesc), "r"(enable), "r"(0u)
        : "memory");
}

// Tile j: group g=j>>2, class j&3: 0=B_hi, 1=A_lo, 2=A_hi, 3=B_lo.
// A tiles: 256 rows x 64 bf16 as two 128-row subtiles (+0 / +16KB).
__device__ __forceinline__ void copy_tile(int j, int tid, uint32_t sbase,
                                          const __nv_bfloat16* A,
                                          const __nv_bfloat16* B,
                                          int m0, int n0) {
    const int g = j >> 2, cls = j & 3;
    const uint32_t base = sbase + (uint32_t)(j % NSLOT) * TILE_B;
    const bool isA = (cls == 1) || (cls == 2);
    const int off = ((cls == 1) || (cls == 3)) ? (2048 + g * 128) : (g * 128);
    const char* src = isA ? ((const char*)A + (size_t)m0 * 4096 + off)
                          : ((const char*)B + (size_t)n0 * 4096 + off);
#pragma unroll
    for (int p = 0; p < 8; p++) {
        int u = tid + p * 256;
        int r = u >> 3, c = u & 7;
        uint32_t dst = isA
            ? (base + (uint32_t)((r >> 7) * 16384) + SWZ128((r & 127) * 128 + c * 16))
            : (base + SWZ128(r * 128 + c * 16));
        cp_async16(dst, src + (size_t)r * 4096 + c * 16);
    }
}
#endif  // HAS_TCGEN05

// ---------------------------------------------------------------------------
// GEMM core (warp-specialized, split-ready pipeline, overlapped prologue)
// ---------------------------------------------------------------------------
__device__ __forceinline__ void gemm_core(const __nv_bfloat16* __restrict__ A,
                                          const __nv_bfloat16* __restrict__ B,
                                          const float* __restrict__ bias,
                                          float* __restrict__ C,
                                          char* smem)
{
    const int tid = threadIdx.x;
    const int m0 = blockIdx.y * BMC;
    const int n0 = blockIdx.x * BN;

#if HAS_TCGEN05
    const uint32_t sbase = smem_u32(smem);

    if (tid < 256) {
        // Producers: start group-0 copies immediately (no barrier/TMEM dep).
        copy_tile(0, tid, sbase, A, B, m0, n0);
        copy_tile(1, tid, sbase, A, B, m0, n0);
        copy_tile(2, tid, sbase, A, B, m0, n0);
        asm volatile("cp.async.commit_group;" ::: "memory");
        copy_tile(3, tid, sbase, A, B, m0, n0);
        asm volatile("cp.async.commit_group;" ::: "memory");
    } else {
        // MMA warp: init barriers + TMEM alloc, overlapped with copies.
        if (elect_one_pred()) {
#pragma unroll
            for (int s = 0; s < 4; s++) {
                MBARRIER_INIT(sbase + MBARA_OFF + s * 8, 1);
                MBARRIER_INIT(sbase + MBARF_OFF + s * 8, 1);
                MBARRIER_INIT(sbase + READY0_OFF + s * 8, 256);
                MBARRIER_INIT(sbase + READY1_OFF + s * 8, 256);
            }
        }
        TCGEN05_ALLOC(sbase + TMEMP_OFF, TMEM_COLS);
        TCGEN05_RELINQUISH();
    }
    __syncthreads();
    uint32_t tmem;
    asm volatile("ld.shared.b32 %0, [%1];" : "=r"(tmem) : "r"(sbase + TMEMP_OFF));

    if (tid < 256) {
        // ======================= producer warps ==========================
        for (int g = 0; g < NGRP; g++) {
            // pending cp.async groups at this point: {A_g, B_g}
            asm volatile("cp.async.wait_group 1;" ::: "memory");   // A_g landed
            MBARRIER_ARRIVE(sbase + READY0_OFF + (g & 3) * 8);
            asm volatile("cp.async.wait_group 0;" ::: "memory");   // B_g landed
            MBARRIER_ARRIVE(sbase + READY1_OFF + (g & 3) * 8);

            if (g + 1 < NGRP) {
                // tiles 4g+4..6 : slots freed by MBARA(g-1), MBARF(g-1)
                if (g >= 1) {
                    MBARRIER_WAIT_PARITY(sbase + MBARA_OFF + ((g - 1) & 3) * 8,
                                         (uint32_t)(((g - 1) >> 2) & 1));
                }
                copy_tile(4 * g + 4, tid, sbase, A, B, m0, n0);
                if (g >= 1) {
                    MBARRIER_WAIT_PARITY(sbase + MBARF_OFF + ((g - 1) & 3) * 8,
                                         (uint32_t)(((g - 1) >> 2) & 1));
                }
                copy_tile(4 * g + 5, tid, sbase, A, B, m0, n0);
                copy_tile(4 * g + 6, tid, sbase, A, B, m0, n0);
                asm volatile("cp.async.commit_group;" ::: "memory");  // A_{g+1}
                // tile 4g+7 : slot freed by MBARA(g) (fires mid-MMA(g))
                MBARRIER_WAIT_PARITY(sbase + MBARA_OFF + (g & 3) * 8,
                                     (uint32_t)((g >> 2) & 1));
                copy_tile(4 * g + 7, tid, sbase, A, B, m0, n0);
                asm volatile("cp.async.commit_group;" ::: "memory");  // B_{g+1}
            }
        }

        // ======================= epilogue (producers) =====================
        MBARRIER_WAIT_PARITY(sbase + MBARF_OFF + ((NGRP - 1) & 3) * 8,
                             (uint32_t)(((NGRP - 1) >> 2) & 1));
        TCGEN05_FENCE_AFTER();
        {
            const int w = tid >> 5, lid = tid & 31;
            const int half = w >> 2;
            const int row  = (w & 3) * 32 + lid;
            const uint32_t dbase = tmem + half * 256;
            float* crow = C + (size_t)(m0 + half * 128 + row) * D_MODEL + n0;
#pragma unroll
            for (int cc = 0; cc < 8; cc += 2) {   // 2 LDTMs in flight per wait
                const int col0 = cc * 32;
                uint32_t d0[32], d1[32];
                TCGEN05_LD_X32(d0, dbase + col0);
                TCGEN05_LD_X32(d1, dbase + col0 + 32);
                TCGEN05_WAIT_LD();
#pragma unroll
                for (int j = 0; j < 32; j += 4) {
                    float4 bv = *(const float4*)(bias + n0 + col0 + j);
                    float4 v;
                    v.x = __uint_as_float(d0[j + 0]) + bv.x;
                    v.y = __uint_as_float(d0[j + 1]) + bv.y;
                    v.z = __uint_as_float(d0[j + 2]) + bv.z;
                    v.w = __uint_as_float(d0[j + 3]) + bv.w;
                    *(float4*)(crow + col0 + j) = v;
                }
#pragma unroll
                for (int j = 0; j < 32; j += 4) {
                    float4 bv = *(const float4*)(bias + n0 + col0 + 32 + j);
                    float4 v;
                    v.x = __uint_as_float(d1[j + 0]) + bv.x;
                    v.y = __uint_as_float(d1[j + 1]) + bv.y;
                    v.z = __uint_as_float(d1[j + 2]) + bv.z;
                    v.w = __uint_as_float(d1[j + 3]) + bv.w;
                    *(float4*)(crow + col0 + 32 + j) = v;
                }
            }
        }
    } else {
        // ========================= MMA warp ===============================
        // Fully unrolled: slot indices and descriptors are compile-time
        // constants, so the first MMA issues right after the barrier wake.
        if (elect_one_pred()) {
#pragma unroll
            for (int g = 0; g < NGRP; g++) {
                const uint32_t par = (uint32_t)((g >> 2) & 1);
                MBARRIER_WAIT_PARITY(sbase + READY0_OFF + (g & 3) * 8, par);
                FENCE_PROXY_ASYNC();
                const uint64_t dBhi = DESC_BASE_SW128 |
                    (((uint64_t)((sbase + (uint32_t)(((4 * g + 0) % NSLOT) * TILE_B)) >> 4)) & 0x3FFF);
                const uint64_t dAlo = DESC_BASE_SW128 |
                    (((uint64_t)((sbase + (uint32_t)(((4 * g + 1) % NSLOT) * TILE_B)) >> 4)) & 0x3FFF);
                const uint64_t dAhi = DESC_BASE_SW128 |
                    (((uint64_t)((sbase + (uint32_t)(((4 * g + 2) % NSLOT) * TILE_B)) >> 4)) & 0x3FFF);
                const uint64_t dBlo = DESC_BASE_SW128 |
                    (((uint64_t)((sbase + (uint32_t)(((4 * g + 3) % NSLOT) * TILE_B)) >> 4)) & 0x3FFF);

                // phase 1: a_hi . b_hi
#pragma unroll
                for (int q = 0; q < 4; q++) {
                    uint32_t en = (uint32_t)((g > 0) || (q > 0));
                    mma_f16_ss_cg1(tmem,       dAhi + 2 * q,        dBhi + 2 * q, IDESC, en);
                    mma_f16_ss_cg1(tmem + 256, dAhi + 1024 + 2 * q, dBhi + 2 * q, IDESC, en);
                }
                // phase 2: a_lo . b_hi
#pragma unroll
                for (int q = 0; q < 4; q++) {
                    mma_f16_ss_cg1(tmem,       dAlo + 2 * q,        dBhi + 2 * q, IDESC, 1);
                    mma_f16_ss_cg1(tmem + 256, dAlo + 1024 + 2 * q, dBhi + 2 * q, IDESC, 1);
                }
                TCGEN05_COMMIT(sbase + MBARA_OFF + (g & 3) * 8);   // frees B_hi, A_lo
                // phase 3: a_hi . b_lo  (needs tile 3)
                MBARRIER_WAIT_PARITY(sbase + READY1_OFF + (g & 3) * 8, par);
                FENCE_PROXY_ASYNC();
#pragma unroll
                for (int q = 0; q < 4; q++) {
                    mma_f16_ss_cg1(tmem,       dAhi + 2 * q,        dBlo + 2 * q, IDESC, 1);
                    mma_f16_ss_cg1(tmem + 256, dAhi + 1024 + 2 * q, dBlo + 2 * q, IDESC, 1);
                }
                TCGEN05_COMMIT(sbase + MBARF_OFF + (g & 3) * 8);   // frees A_hi, B_lo
            }
        }
    }

    __syncthreads();
    if (tid < 32) TCGEN05_DEALLOC(tmem, TMEM_COLS);

#else
    // ================== wmma bf16 fallback (plain sm_103) =================
    using namespace nvcuda;
    using FA = wmma::fragment<wmma::matrix_a, 16, 16, 16, __nv_bfloat16, wmma::row_major>;
    using FB = wmma::fragment<wmma::matrix_b, 16, 16, 16, __nv_bfloat16, wmma::col_major>;
    using FC = wmma::fragment<wmma::accumulator, 16, 16, 16, float>;

    constexpr int BKF  = 32;
    constexpr int LDF  = BKF + 8;
    constexpr int LDCF = 128 + 4;

    __nv_bfloat16* As = (__nv_bfloat16*)smem;
    __nv_bfloat16* Bs = As + 128 * LDF;
    float*         Cs = (float*)smem;

    const int warp = tid >> 5;
    const int wm = warp >> 1;
    const int wn = warp & 1;
    const bool active = (tid < 256);

    for (int mt = 0; mt < 2; mt++) {
        const int m0h = m0 + mt * 128;
        for (int half = 0; half < 2; half++) {
            const int n0h = n0 + half * 128;
            FC acc[2][4];
#pragma unroll
            for (int a = 0; a < 2; a++)
#pragma unroll
                for (int b = 0; b < 4; b++) wmma::fill_fragment(acc[a][b], 0.0f);

            for (int term = 0; term < 3; term++) {
                const int aoff = (term == 1) ? 1024 : 0;
                const int boff = (term == 2) ? 1024 : 0;
                for (int kt = 0; kt < 1024; kt += BKF) {
                    if (active) {
#pragma unroll
                        for (int p = 0; p < 2; p++) {
                            int idx = tid + p * 256;
                            int r = idx >> 2, cidx = idx & 3;
                            *(uint4*)(As + r * LDF + cidx * 8) =
                                *(const uint4*)(A + (size_t)(m0h + r) * KA + aoff + kt + cidx * 8);
                            *(uint4*)(Bs + r * LDF + cidx * 8) =
                                *(const uint4*)(B + (size_t)(n0h + r) * KA + boff + kt + cidx * 8);
                        }
                    }
                    __syncthreads();
                    if (active) {
#pragma unroll
                        for (int kk = 0; kk < BKF; kk += 16) {
                            FA af[2];
                            FB bf[4];
#pragma unroll
                            for (int mi = 0; mi < 2; mi++)
                                wmma::load_matrix_sync(af[mi], As + (wm * 32 + mi * 16) * LDF + kk, LDF);
#pragma unroll
                            for (int ni = 0; ni < 4; ni++)
                                wmma::load_matrix_sync(bf[ni], Bs + (wn * 64 + ni * 16) * LDF + kk, LDF);
#pragma unroll
                            for (int mi = 0; mi < 2; mi++)
#pragma unroll
                                for (int ni = 0; ni < 4; ni++)
                                    wmma::mma_sync(acc[mi][ni], af[mi], bf[ni], acc[mi][ni]);
                        }
                    }
                    __syncthreads();
                }
            }

            if (active) {
#pragma unroll
                for (int mi = 0; mi < 2; mi++)
#pragma unroll
                    for (int ni = 0; ni < 4; ni++)
                        wmma::store_matrix_sync(Cs + (wm * 32 + mi * 16) * LDCF + wn * 64 + ni * 16,
                                                acc[mi][ni], LDCF, wmma::mem_row_major);
            }
            __syncthreads();

            if (active) {
                const int c4 = tid & 31;
                const int r0 = tid >> 5;
                float4 bv = *(const float4*)(bias + n0h + c4 * 4);
#pragma unroll
                for (int rr = 0; rr < 128; rr += 8) {
                    int r = rr + r0;
                    float4 v = *(float4*)(Cs + r * LDCF + c4 * 4);
                    v.x += bv.x; v.y += bv.y; v.z += bv.z; v.w += bv.w;
                    *(float4*)(C + (size_t)(m0h + r) * D_MODEL + n0h + c4 * 4) = v;
                }
            }
            __syncthreads();
        }
    }
#endif
}

// Fused QKV GEMM. grid (4,64,3), 288 threads
__global__ void __launch_bounds__(GEMM_THREADS, 1)
gemm_qkv(const __nv_bfloat16* __restrict__ a0, const __nv_bfloat16* __restrict__ a1,
         const __nv_bfloat16* __restrict__ a2,
         const __nv_bfloat16* __restrict__ w0, const __nv_bfloat16* __restrict__ w1,
         const __nv_bfloat16* __restrict__ w2,
         const float* __restrict__ bq, const float* __restrict__ bk,
         const float* __restrict__ bv,
         float* __restrict__ cq, float* __restrict__ ck, float* __restrict__ cv)
{
    extern __shared__ __align__(1024) char smem[];
    const int z = blockIdx.z;
    const __nv_bfloat16* A = (z == 0) ? a0 : (z == 1) ? a1 : a2;
    const __nv_bfloat16* W = (z == 0) ? w0 : (z == 1) ? w1 : w2;
    const float* bias      = (z == 0) ? bq : (z == 1) ? bk : bv;
    float* C               = (z == 0) ? cq : (z == 1) ? ck : cv;
    gemm_core(A, W, bias, C, smem);
}

// Single GEMM (output projection). grid (4,64), 288 threads
__global__ void __launch_bounds__(GEMM_THREADS, 1)
gemm_one(const __nv_bfloat16* __restrict__ A, const __nv_bfloat16* __restrict__ W,
         const float* __restrict__ bias, float* __restrict__ C)
{
    extern __shared__ __align__(1024) char smem[];
    gemm_core(A, W, bias, C, smem);
}

// ---------------------------------------------------------------------------
// Fused split: weights (blocks 0..4095) + activations (blocks 4096..53247)
// fp32 -> [hi|lo] bf16, width 2048. One launch.
// ---------------------------------------------------------------------------
__global__ void __launch_bounds__(256)
split_all(const float* __restrict__ w0, const float* __restrict__ w1,
          const float* __restrict__ w2, const float* __restrict__ w3,
          __nv_bfloat16* __restrict__ o0, __nv_bfloat16* __restrict__ o1,
          __nv_bfloat16* __restrict__ o2, __nv_bfloat16* __restrict__ o3,
          const float* __restrict__ q, const float* __restrict__ k,
          const float* __restrict__ v,
          __nv_bfloat16* __restrict__ oq, __nv_bfloat16* __restrict__ ok,
          __nv_bfloat16* __restrict__ ov)
{
    const int b = blockIdx.x;
    const float* in;
    __nv_bfloat16* out;
    size_t row;
    if (b < 4096) {                       // weights
        const int which = b >> 10;
        row = (size_t)(b & 1023);
        in  = (which == 0) ? w0 : (which == 1) ? w1 : (which == 2) ? w2 : w3;
        out = (which == 0) ? o0 : (which == 1) ? o1 : (which == 2) ? o2 : o3;
    } else {                              // activations
        const int idx = b - 4096;
        const int which = idx >> 14;
        row = (size_t)(idx & 16383);
        in  = (which == 0) ? q : (which == 1) ? k : v;
        out = (which == 0) ? oq : (which == 1) ? ok : ov;
    }

    const int col = threadIdx.x * 4;
    uint2 hi, lo;
    split_row4(*(const float4*)(in + row * D_MODEL + col), hi, lo);
    *(uint2*)(out + row * KA + col)           = hi;
    *(uint2*)(out + row * KA + D_MODEL + col) = lo;
}

// ---------------------------------------------------------------------------
// Per-token "attention" mix; writes X directly as [hi|lo] bf16 split.
// (R14 formulation: 4 strided oi per thread, scalar vs reads - measured best.)
// ---------------------------------------------------------------------------
__global__ void __launch_bounds__(256)
attn_mix_split(const float* __restrict__ Q,
               const float* __restrict__ K,
               const float* __restrict__ V,
               const int*   __restrict__ mask,
               __nv_bfloat16* __restrict__ Xs)
{
    __shared__ __align__(16) float qs[D_MODEL];
    __shared__ __align__(16) float vs[D_MODEL];
    __shared__ __align__(16) float kT[D_MODEL];
    __shared__ float a_s[NUM_HEADS * NUM_HEADS];

    const int t = threadIdx.x;
    const size_t base = (size_t)blockIdx.x * D_MODEL;

    float4 q4 = *(const float4*)(Q + base + t * 4);
    float4 v4 = *(const float4*)(V + base + t * 4);
    float4 k4 = *(const float4*)(K + base + t * 4);
    *(float4*)(qs + t * 4) = q4;
    *(float4*)(vs + t * 4) = v4;
    {   // vectorized swizzled transpose: 4 consecutive d share l and d>>2
        int j = t * 4;
        int d0 = j & 63, l0 = j >> 6;
        int x = l0 ^ (d0 >> 2);
        *(float4*)(kT + (d0 >> 2) * 64 + x * 4) = k4;
    }
    __syncthreads();

    const int i = t >> 4, l = t & 15;
    float e = 0.0f;
#pragma unroll
    for (int d = 0; d < HEAD_DIM; d += 4) {
        float4 qv = *(const float4*)(qs + i * 64 + d);
        float4 kv = *(const float4*)(kT + (d >> 2) * 64 + (l ^ (d >> 2)) * 4);
        e += qv.x * kv.x + qv.y * kv.y + qv.z * kv.z + qv.w * kv.w;
    }

    const int mk = mask[blockIdx.x];
    e = mk ? e * 0.03125f : 0.0f;         // 1/sqrt(1024); masked -> uniform

    float mx = e;
#pragma unroll
    for (int off = 8; off; off >>= 1)
        mx = fmaxf(mx, __shfl_xor_sync(0xffffffffu, mx, off, 16));
    float p = expf(e - mx);
    float s = p;
#pragma unroll
    for (int off = 8; off; off >>= 1)
        s += __shfl_xor_sync(0xffffffffu, s, off, 16);
    a_s[t] = p / s;
    __syncthreads();

    const int od = t & 63;
    const int oib = t >> 6;
    float acc0 = 0.f, acc1 = 0.f, acc2 = 0.f, acc3 = 0.f;
#pragma unroll
    for (int ll = 0; ll < 16; ll++) {
        float vv = vs[ll * 64 + od];
        acc0 += a_s[(0 * 4 + oib) * 16 + ll] * vv;
        acc1 += a_s[(1 * 4 + oib) * 16 + ll] * vv;
        acc2 += a_s[(2 * 4 + oib) * 16 + ll] * vv;
        acc3 += a_s[(3 * 4 + oib) * 16 + ll] * vv;
    }
    const size_t obase = (size_t)blockIdx.x * KA;
    float accs[4] = {acc0, acc1, acc2, acc3};
#pragma unroll
    for (int r = 0; r < 4; r++) {
        int o = r * 256 + t;
        __nv_bfloat16 h  = __float2bfloat16(accs[r]);
        __nv_bfloat16 lo = __float2bfloat16(accs[r] - __bfloat162float(h));
        Xs[obase + o]           = h;
        Xs[obase + D_MODEL + o] = lo;
    }
}

// ---------------------------------------------------------------------------
// Launch
// ---------------------------------------------------------------------------
extern "C" void kernel_launch(void* const* d_in, const int* in_sizes, int n_in,
                              void* d_out, int out_size)
{
    (void)in_sizes; (void)n_in; (void)out_size;
    const float* query = (const float*)d_in[0];
    const float* key   = (const float*)d_in[1];
    const float* value = (const float*)d_in[2];
    const int*   mask  = (const int*)  d_in[3];
    const float* Wq = (const float*)d_in[4];
    const float* bq = (const float*)d_in[5];
    const float* Wk = (const float*)d_in[6];
    const float* bk = (const float*)d_in[7];
    const float* Wv = (const float*)d_in[8];
    const float* bv = (const float*)d_in[9];
    const float* Wo = (const float*)d_in[10];
    const float* bo = (const float*)d_in[11];
    float* out = (float*)d_out;

    void *pQ, *pK, *pV, *pA0, *pA1, *pA2, *pW0, *pW1, *pW2, *pW3;
    cudaGetSymbolAddress(&pQ, g_Q);
    cudaGetSymbolAddress(&pK, g_K);
    cudaGetSymbolAddress(&pV, g_V);
    cudaGetSymbolAddress(&pA0, g_a0);
    cudaGetSymbolAddress(&pA1, g_a1);
    cudaGetSymbolAddress(&pA2, g_a2);
    cudaGetSymbolAddress(&pW0, g_w0);
    cudaGetSymbolAddress(&pW1, g_w1);
    cudaGetSymbolAddress(&pW2, g_w2);
    cudaGetSymbolAddress(&pW3, g_w3);

    cudaFuncSetAttribute(gemm_qkv,
                         cudaFuncAttributeMaxDynamicSharedMemorySize, SMEM_TOTAL);
    cudaFuncSetAttribute(gemm_one,
                         cudaFuncAttributeMaxDynamicSharedMemorySize, SMEM_TOTAL);

    split_all<<<4096 + 3 * M_TOK, 256>>>(
        Wq, Wk, Wv, Wo,
        (__nv_bfloat16*)pW0, (__nv_bfloat16*)pW1,
        (__nv_bfloat16*)pW2, (__nv_bfloat16*)pW3,
        query, key, value,
        (__nv_bfloat16*)pA0, (__nv_bfloat16*)pA1, (__nv_bfloat16*)pA2);

    dim3 qkvgrid(D_MODEL / BN, M_TOK / BMC, 3);   // (4, 64, 3)
    gemm_qkv<<<qkvgrid, GEMM_THREADS, SMEM_TOTAL>>>(
        (__nv_bfloat16*)pA0, (__nv_bfloat16*)pA1, (__nv_bfloat16*)pA2,
        (__nv_bfloat16*)pW0, (__nv_bfloat16*)pW1, (__nv_bfloat16*)pW2,
        bq, bk, bv, (float*)pQ, (float*)pK, (float*)pV);

    attn_mix_split<<<M_TOK, 256>>>((const float*)pQ, (const float*)pK,
                                   (const float*)pV, mask, (__nv_bfloat16*)pA0);

    dim3 ogrid(D_MODEL / BN, M_TOK / BMC);        // (4, 64)
    gemm_one<<<ogrid, GEMM_THREADS, SMEM_TOTAL>>>((__nv_bfloat16*)pA0,
                                                  (__nv_bfloat16*)pW3, bo, out);
}

// round 17
// speedup vs baseline: 1.0407x; 1.0151x over previous
#include <cuda_runtime.h>
#include <cuda_bf16.h>
#include <mma.h>
#include <cstdint>

// ---------------------------------------------------------------------------
// Arch-feature gate: tcgen05 only legal in sm_103a/sm_100a PTX. The
// compute_103 (no 'a') pass compiles a correct wmma-bf16 fallback.
// ---------------------------------------------------------------------------
#if defined(__CUDA_ARCH__) && \
    (defined(__CUDA_ARCH_FEAT_SM103_ALL) || defined(__CUDA_ARCH_FEAT_SM100_ALL) || \
     (defined(__CUDA_ARCH_SPECIFIC__)        && (__CUDA_ARCH_SPECIFIC__ >= 1000)) || \
     (defined(__CUDA_ARCH_FAMILY_SPECIFIC__) && (__CUDA_ARCH_FAMILY_SPECIFIC__ >= 1000)))
#define HAS_TCGEN05 1
#else
#define HAS_TCGEN05 0
#endif

// ---------------------------------------------------------------------------
// Problem constants
// ---------------------------------------------------------------------------
constexpr int D_MODEL   = 1024;
constexpr int NUM_HEADS = 16;
constexpr int HEAD_DIM  = 64;
constexpr int M_TOK     = 16384;

// 3-term bf16 split: C = a_hi.b_hi + a_lo.b_hi + a_hi.b_lo  (err ~2^-18)
constexpr int KA = 2 * D_MODEL;   // 2048 pack width (acts AND weights)

// GEMM tiling: per CTA 256 M x 256 N (two 128-row MMA subtiles), 16 K-groups.
constexpr int BMC = 256;
constexpr int BN  = 256;
constexpr int NGRP = 16;
constexpr int GEMM_THREADS = 288;  // 8 producer warps + 1 MMA warp

constexpr int TILE_B   = 32768;   // one tile: 256 rows x 128 bytes
constexpr int NSLOT    = 7;       // ring of 7 tiles = 224 KB
constexpr int BAR_OFF    = NSLOT * TILE_B;     // 229376
constexpr int MBARA_OFF  = BAR_OFF;            // 4 x 8B (phase-A commits)
constexpr int MBARF_OFF  = BAR_OFF + 32;       // 4 x 8B (full commits)
constexpr int READY0_OFF = BAR_OFF + 64;       // 4 x 8B (tiles 0-2 landed)
constexpr int READY1_OFF = BAR_OFF + 96;       // 4 x 8B (tile 3 landed)
constexpr int TMEMP_OFF  = BAR_OFF + 128;
constexpr int SMEM_TOTAL = BAR_OFF + 136;      // 229512 <= 232448 cap

constexpr int TMEM_COLS = 512;

// idesc kind::f16 cg1: dtype=F32, a/b=BF16, N=256, M=128
constexpr uint32_t IDESC =
    (1u << 4) | (1u << 7) | (1u << 10) | ((BN / 8) << 17) | ((128 / 16) << 24);

// SW128 K-major smem descriptor base (layout=SW128, version=1, SBO=64, LBO=1)
constexpr uint64_t DESC_BASE_SW128 =
    (uint64_t(2) << 61) | (uint64_t(1) << 46) | (uint64_t(64) << 32) | (uint64_t(1) << 16);

// ---------------------------------------------------------------------------
// Scratch (device globals: allocation-free, graph-capture safe)
// ---------------------------------------------------------------------------
__device__ float          g_Q[M_TOK * D_MODEL];
__device__ float          g_K[M_TOK * D_MODEL];
__device__ float          g_V[M_TOK * D_MODEL];
__device__ __nv_bfloat16  g_a0[(size_t)M_TOK * KA];   // query split / X split
__device__ __nv_bfloat16  g_a1[(size_t)M_TOK * KA];   // key split
__device__ __nv_bfloat16  g_a2[(size_t)M_TOK * KA];   // value split
__device__ __nv_bfloat16  g_w0[(size_t)D_MODEL * KA];
__device__ __nv_bfloat16  g_w1[(size_t)D_MODEL * KA];
__device__ __nv_bfloat16  g_w2[(size_t)D_MODEL * KA];
__device__ __nv_bfloat16  g_w3[(size_t)D_MODEL * KA];

// ---------------------------------------------------------------------------
// Helpers
// ---------------------------------------------------------------------------
__device__ __forceinline__ uint32_t smem_u32(const void* p) {
    return (uint32_t)__cvta_generic_to_shared(p);
}
__device__ __forceinline__ uint32_t elect_one_pred() {
    uint32_t pred;
    asm volatile("{\n\t.reg .pred p;\n\telect.sync _|p, 0xFFFFFFFF;\n\t"
                 "selp.b32 %0, 1, 0, p;\n\t}" : "=r"(pred));
    return pred;
}
#define SWZ128(x) ((x) ^ (((x) >> 3) & 0x70))

#define MBARRIER_INIT(addr, cnt) \
    asm volatile("mbarrier.init.shared.b64 [%0], %1;" :: "r"(addr), "r"((uint32_t)(cnt)) : "memory")
#define MBARRIER_ARRIVE(addr) \
    asm volatile("mbarrier.arrive.shared.b64 _, [%0];" :: "r"(addr) : "memory")

#define MBARRIER_WAIT_PARITY(addr, par) do {                                      \
    uint32_t _m = (addr); uint32_t _p = (par); uint32_t _d;                       \
    asm volatile("{\n\t.reg .pred p;\n\t"                                         \
        "mbarrier.try_wait.parity.acquire.cta.shared::cta.b64 p, [%1], %2;\n\t"   \
        "selp.b32 %0, 1, 0, p;\n\t}" : "=r"(_d) : "r"(_m), "r"(_p) : "memory");   \
    if (!_d) {                                                                    \
        asm volatile("{\n\t.reg .pred P1;\n\t"                                    \
        "WL_%=:\n\t"                                                              \
        "mbarrier.try_wait.parity.acquire.cta.shared::cta.b64 P1, [%0], %1, 0x989680;\n\t" \
        "@P1 bra.uni WD_%=;\n\t"                                                  \
        "bra.uni WL_%=;\n\t"                                                      \
        "WD_%=:\n\t}" :: "r"(_m), "r"(_p) : "memory");                            \
    }                                                                             \
} while (0)

__device__ __forceinline__ void cp_async16(uint32_t dst, const void* src) {
    asm volatile("cp.async.cg.shared.global [%0], [%1], 16;"
                 :: "r"(dst), "l"(src) : "memory");
}

__device__ __forceinline__ void split_row4(float4 v, uint2& hi, uint2& lo) {
    __nv_bfloat162 h01 = __float22bfloat162_rn(make_float2(v.x, v.y));
    __nv_bfloat162 h23 = __float22bfloat162_rn(make_float2(v.z, v.w));
    float2 r01 = make_float2(v.x - __low2float(h01), v.y - __high2float(h01));
    float2 r23 = make_float2(v.z - __low2float(h23), v.w - __high2float(h23));
    __nv_bfloat162 l01 = __float22bfloat162_rn(r01);
    __nv_bfloat162 l23 = __float22bfloat162_rn(r23);
    hi.x = *(uint32_t*)&h01; hi.y = *(uint32_t*)&h23;
    lo.x = *(uint32_t*)&l01; lo.y = *(uint32_t*)&l23;
}

#if HAS_TCGEN05
#define TCGEN05_ALLOC(smem_addr, ncols) \
    asm volatile("tcgen05.alloc.cta_group::1.sync.aligned.shared::cta.b32 [%0], %1;" \
                 :: "r"(smem_addr), "r"((uint32_t)(ncols)) : "memory")
#define TCGEN05_RELINQUISH() \
    asm volatile("tcgen05.relinquish_alloc_permit.cta_group::1.sync.aligned;")
#define TCGEN05_DEALLOC(tmem, ncols) \
    asm volatile("tcgen05.dealloc.cta_group::1.sync.aligned.b32 %0, %1;" \
                 :: "r"(tmem), "r"((uint32_t)(ncols)))
#define TCGEN05_COMMIT(mbar) \
    asm volatile("tcgen05.commit.cta_group::1.mbarrier::arrive::one.shared::cluster.b64 [%0];" \
                 :: "r"(mbar) : "memory")
#define TCGEN05_FENCE_AFTER() \
    asm volatile("tcgen05.fence::after_thread_sync;" ::: "memory")
#define TCGEN05_WAIT_LD() \
    asm volatile("tcgen05.wait::ld.sync.aligned;" ::: "memory")
#define FENCE_PROXY_ASYNC() \
    asm volatile("fence.proxy.async.shared::cta;" ::: "memory")

#define TCGEN05_LD_X32(r, addr)                                              \
    asm volatile("tcgen05.ld.sync.aligned.32x32b.x32.b32 "                   \
        "{%0, %1, %2, %3, %4, %5, %6, %7, "                                  \
        " %8, %9, %10, %11, %12, %13, %14, %15, "                            \
        " %16, %17, %18, %19, %20, %21, %22, %23, "                          \
        " %24, %25, %26, %27, %28, %29, %30, %31}, [%32];"                   \
        : "=r"((r)[0]),  "=r"((r)[1]),  "=r"((r)[2]),  "=r"((r)[3]),         \
          "=r"((r)[4]),  "=r"((r)[5]),  "=r"((r)[6]),  "=r"((r)[7]),         \
          "=r"((r)[8]),  "=r"((r)[9]),  "=r"((r)[10]), "=r"((r)[11]),        \
          "=r"((r)[12]), "=r"((r)[13]), "=r"((r)[14]), "=r"((r)[15]),        \
          "=r"((r)[16]), "=r"((r)[17]), "=r"((r)[18]), "=r"((r)[19]),        \
          "=r"((r)[20]), "=r"((r)[21]), "=r"((r)[22]), "=r"((r)[23]),        \
          "=r"((r)[24]), "=r"((r)[25]), "=r"((r)[26]), "=r"((r)[27]),        \
          "=r"((r)[28]), "=r"((r)[29]), "=r"((r)[30]), "=r"((r)[31])         \
        : "r"(addr))

__device__ __forceinline__ void mma_f16_ss_cg1(uint32_t d_tmem, uint64_t adesc,
                                               uint64_t bdesc, uint32_t idesc,
                                               uint32_t enable) {
    asm volatile(
        "{\n\t.reg .pred p;\n\tsetp.ne.u32 p, %4, 0;\n\t"
        "tcgen05.mma.cta_group::1.kind::f16 [%0], %1, %2, %3, {%5,%5,%5,%5}, p;\n\t}"
        :: "r"(d_tmem), "l"(adesc), "l"(bdesc), "r"(idesc), "r"(enable), "r"(0u)
        : "memory");
}

// Tile j: group g=j>>2, class j&3: 0=B_hi, 1=A_lo, 2=A_hi, 3=B_lo.
// A tiles: 256 rows x 64 bf16 as two 128-row subtiles (+0 / +16KB).
__device__ __forceinline__ void copy_tile(int j, int tid, uint32_t sbase,
                                          const __nv_bfloat16* A,
                                          const __nv_bfloat16* B,
                                          int m0, int n0) {
    const int g = j >> 2, cls = j & 3;
    const uint32_t base = sbase + (uint32_t)(j % NSLOT) * TILE_B;
    const bool isA = (cls == 1) || (cls == 2);
    const int off = ((cls == 1) || (cls == 3)) ? (2048 + g * 128) : (g * 128);
    const char* src = isA ? ((const char*)A + (size_t)m0 * 4096 + off)
                          : ((const char*)B + (size_t)n0 * 4096 + off);
#pragma unroll
    for (int p = 0; p < 8; p++) {
        int u = tid + p * 256;
        int r = u >> 3, c = u & 7;
        uint32_t dst = isA
            ? (base + (uint32_t)((r >> 7) * 16384) + SWZ128((r & 127) * 128 + c * 16))
            : (base + SWZ128(r * 128 + c * 16));
        cp_async16(dst, src + (size_t)r * 4096 + c * 16);
    }
}
#endif  // HAS_TCGEN05

// ---------------------------------------------------------------------------
// GEMM core (warp-specialized, split-ready pipeline)
// ---------------------------------------------------------------------------
__device__ __forceinline__ void gemm_core(const __nv_bfloat16* __restrict__ A,
                                          const __nv_bfloat16* __restrict__ B,
                                          const float* __restrict__ bias,
                                          float* __restrict__ C,
                                          char* smem)
{
    const int tid = threadIdx.x;
    const int m0 = blockIdx.y * BMC;
    const int n0 = blockIdx.x * BN;

#if HAS_TCGEN05
    const uint32_t sbase = smem_u32(smem);

    if (tid == 0) {
#pragma unroll
        for (int s = 0; s < 4; s++) {
            MBARRIER_INIT(sbase + MBARA_OFF + s * 8, 1);
            MBARRIER_INIT(sbase + MBARF_OFF + s * 8, 1);
            MBARRIER_INIT(sbase + READY0_OFF + s * 8, 256);
            MBARRIER_INIT(sbase + READY1_OFF + s * 8, 256);
        }
    }
    if (tid < 32) {
        TCGEN05_ALLOC(sbase + TMEMP_OFF, TMEM_COLS);
        TCGEN05_RELINQUISH();
    }
    __syncthreads();
    uint32_t tmem;
    asm volatile("ld.shared.b32 %0, [%1];" : "=r"(tmem) : "r"(sbase + TMEMP_OFF));

    if (tid < 256) {
        // ======================= producer warps ==========================
        // prologue: group 0, two commit-groups (tiles 0-2, tile 3)
        copy_tile(0, tid, sbase, A, B, m0, n0);
        copy_tile(1, tid, sbase, A, B, m0, n0);
        copy_tile(2, tid, sbase, A, B, m0, n0);
        asm volatile("cp.async.commit_group;" ::: "memory");
        copy_tile(3, tid, sbase, A, B, m0, n0);
        asm volatile("cp.async.commit_group;" ::: "memory");

        for (int g = 0; g < NGRP; g++) {
            // pending cp.async groups at this point: {A_g, B_g}
            asm volatile("cp.async.wait_group 1;" ::: "memory");   // A_g landed
            MBARRIER_ARRIVE(sbase + READY0_OFF + (g & 3) * 8);
            asm volatile("cp.async.wait_group 0;" ::: "memory");   // B_g landed
            MBARRIER_ARRIVE(sbase + READY1_OFF + (g & 3) * 8);

            if (g + 1 < NGRP) {
                // tiles 4g+4..6 : slots freed by MBARA(g-1), MBARF(g-1)
                if (g >= 1) {
                    MBARRIER_WAIT_PARITY(sbase + MBARA_OFF + ((g - 1) & 3) * 8,
                                         (uint32_t)(((g - 1) >> 2) & 1));
                }
                copy_tile(4 * g + 4, tid, sbase, A, B, m0, n0);
                if (g >= 1) {
                    MBARRIER_WAIT_PARITY(sbase + MBARF_OFF + ((g - 1) & 3) * 8,
                                         (uint32_t)(((g - 1) >> 2) & 1));
                }
                copy_tile(4 * g + 5, tid, sbase, A, B, m0, n0);
                copy_tile(4 * g + 6, tid, sbase, A, B, m0, n0);
                asm volatile("cp.async.commit_group;" ::: "memory");  // A_{g+1}
                // tile 4g+7 : slot freed by MBARA(g) (fires mid-MMA(g))
                MBARRIER_WAIT_PARITY(sbase + MBARA_OFF + (g & 3) * 8,
                                     (uint32_t)((g >> 2) & 1));
                copy_tile(4 * g + 7, tid, sbase, A, B, m0, n0);
                asm volatile("cp.async.commit_group;" ::: "memory");  // B_{g+1}
            }
        }

        // ======================= epilogue (producers) =====================
        MBARRIER_WAIT_PARITY(sbase + MBARF_OFF + ((NGRP - 1) & 3) * 8,
                             (uint32_t)(((NGRP - 1) >> 2) & 1));
        TCGEN05_FENCE_AFTER();
        {
            const int w = tid >> 5, lid = tid & 31;
            const int half = w >> 2;
            const int row  = (w & 3) * 32 + lid;
            const uint32_t dbase = tmem + half * 256;
            float* crow = C + (size_t)(m0 + half * 128 + row) * D_MODEL + n0;
#pragma unroll
            for (int cc = 0; cc < 8; cc++) {
                const int col0 = cc * 32;
                uint32_t d[32];
                TCGEN05_LD_X32(d, dbase + col0);
                TCGEN05_WAIT_LD();
#pragma unroll
                for (int j = 0; j < 32; j += 4) {
                    float4 v;
                    v.x = __uint_as_float(d[j + 0]) + __ldg(bias + n0 + col0 + j + 0);
                    v.y = __uint_as_float(d[j + 1]) + __ldg(bias + n0 + col0 + j + 1);
                    v.z = __uint_as_float(d[j + 2]) + __ldg(bias + n0 + col0 + j + 2);
                    v.w = __uint_as_float(d[j + 3]) + __ldg(bias + n0 + col0 + j + 3);
                    *(float4*)(crow + col0 + j) = v;
                }
            }
        }
    } else {
        // ========================= MMA warp ===============================
        if (elect_one_pred()) {
            for (int g = 0; g < NGRP; g++) {
                const uint32_t par = (uint32_t)((g >> 2) & 1);
                MBARRIER_WAIT_PARITY(sbase + READY0_OFF + (g & 3) * 8, par);
                FENCE_PROXY_ASYNC();
                const uint64_t dBhi = DESC_BASE_SW128 |
                    (((uint64_t)((sbase + (uint32_t)(((4 * g + 0) % NSLOT) * TILE_B)) >> 4)) & 0x3FFF);
                const uint64_t dAlo = DESC_BASE_SW128 |
                    (((uint64_t)((sbase + (uint32_t)(((4 * g + 1) % NSLOT) * TILE_B)) >> 4)) & 0x3FFF);
                const uint64_t dAhi = DESC_BASE_SW128 |
                    (((uint64_t)((sbase + (uint32_t)(((4 * g + 2) % NSLOT) * TILE_B)) >> 4)) & 0x3FFF);
                const uint64_t dBlo = DESC_BASE_SW128 |
                    (((uint64_t)((sbase + (uint32_t)(((4 * g + 3) % NSLOT) * TILE_B)) >> 4)) & 0x3FFF);

                // phase 1: a_hi . b_hi
#pragma unroll
                for (int q = 0; q < 4; q++) {
                    uint32_t en = (uint32_t)((g > 0) || (q > 0));
                    mma_f16_ss_cg1(tmem,       dAhi + 2 * q,        dBhi + 2 * q, IDESC, en);
                    mma_f16_ss_cg1(tmem + 256, dAhi + 1024 + 2 * q, dBhi + 2 * q, IDESC, en);
                }
                // phase 2: a_lo . b_hi
#pragma unroll
                for (int q = 0; q < 4; q++) {
                    mma_f16_ss_cg1(tmem,       dAlo + 2 * q,        dBhi + 2 * q, IDESC, 1);
                    mma_f16_ss_cg1(tmem + 256, dAlo + 1024 + 2 * q, dBhi + 2 * q, IDESC, 1);
                }
                TCGEN05_COMMIT(sbase + MBARA_OFF + (g & 3) * 8);   // frees B_hi, A_lo
                // phase 3: a_hi . b_lo  (needs tile 3)
                MBARRIER_WAIT_PARITY(sbase + READY1_OFF + (g & 3) * 8, par);
                FENCE_PROXY_ASYNC();
#pragma unroll
                for (int q = 0; q < 4; q++) {
                    mma_f16_ss_cg1(tmem,       dAhi + 2 * q,        dBlo + 2 * q, IDESC, 1);
                    mma_f16_ss_cg1(tmem + 256, dAhi + 1024 + 2 * q, dBlo + 2 * q, IDESC, 1);
                }
                TCGEN05_COMMIT(sbase + MBARF_OFF + (g & 3) * 8);   // frees A_hi, B_lo
            }
        }
    }

    __syncthreads();
    if (tid < 32) TCGEN05_DEALLOC(tmem, TMEM_COLS);

#else
    // ================== wmma bf16 fallback (plain sm_103) =================
    using namespace nvcuda;
    using FA = wmma::fragment<wmma::matrix_a, 16, 16, 16, __nv_bfloat16, wmma::row_major>;
    using FB = wmma::fragment<wmma::matrix_b, 16, 16, 16, __nv_bfloat16, wmma::col_major>;
    using FC = wmma::fragment<wmma::accumulator, 16, 16, 16, float>;

    constexpr int BKF  = 32;
    constexpr int LDF  = BKF + 8;
    constexpr int LDCF = 128 + 4;

    __nv_bfloat16* As = (__nv_bfloat16*)smem;
    __nv_bfloat16* Bs = As + 128 * LDF;
    float*         Cs = (float*)smem;

    const int warp = tid >> 5;
    const int wm = warp >> 1;
    const int wn = warp & 1;
    const bool active = (tid < 256);

    for (int mt = 0; mt < 2; mt++) {
        const int m0h = m0 + mt * 128;
        for (int half = 0; half < 2; half++) {
            const int n0h = n0 + half * 128;
            FC acc[2][4];
#pragma unroll
            for (int a = 0; a < 2; a++)
#pragma unroll
                for (int b = 0; b < 4; b++) wmma::fill_fragment(acc[a][b], 0.0f);

            for (int term = 0; term < 3; term++) {
                const int aoff = (term == 1) ? 1024 : 0;
                const int boff = (term == 2) ? 1024 : 0;
                for (int kt = 0; kt < 1024; kt += BKF) {
                    if (active) {
#pragma unroll
                        for (int p = 0; p < 2; p++) {
                            int idx = tid + p * 256;
                            int r = idx >> 2, cidx = idx & 3;
                            *(uint4*)(As + r * LDF + cidx * 8) =
                                *(const uint4*)(A + (size_t)(m0h + r) * KA + aoff + kt + cidx * 8);
                            *(uint4*)(Bs + r * LDF + cidx * 8) =
                                *(const uint4*)(B + (size_t)(n0h + r) * KA + boff + kt + cidx * 8);
                        }
                    }
                    __syncthreads();
                    if (active) {
#pragma unroll
                        for (int kk = 0; kk < BKF; kk += 16) {
                            FA af[2];
                            FB bf[4];
#pragma unroll
                            for (int mi = 0; mi < 2; mi++)
                                wmma::load_matrix_sync(af[mi], As + (wm * 32 + mi * 16) * LDF + kk, LDF);
#pragma unroll
                            for (int ni = 0; ni < 4; ni++)
                                wmma::load_matrix_sync(bf[ni], Bs + (wn * 64 + ni * 16) * LDF + kk, LDF);
#pragma unroll
                            for (int mi = 0; mi < 2; mi++)
#pragma unroll
                                for (int ni = 0; ni < 4; ni++)
                                    wmma::mma_sync(acc[mi][ni], af[mi], bf[ni], acc[mi][ni]);
                        }
                    }
                    __syncthreads();
                }
            }

            if (active) {
#pragma unroll
                for (int mi = 0; mi < 2; mi++)
#pragma unroll
                    for (int ni = 0; ni < 4; ni++)
                        wmma::store_matrix_sync(Cs + (wm * 32 + mi * 16) * LDCF + wn * 64 + ni * 16,
                                                acc[mi][ni], LDCF, wmma::mem_row_major);
            }
            __syncthreads();

            if (active) {
                const int c4 = tid & 31;
                const int r0 = tid >> 5;
                float4 bv = *(const float4*)(bias + n0h + c4 * 4);
#pragma unroll
                for (int rr = 0; rr < 128; rr += 8) {
                    int r = rr + r0;
                    float4 v = *(float4*)(Cs + r * LDCF + c4 * 4);
                    v.x += bv.x; v.y += bv.y; v.z += bv.z; v.w += bv.w;
                    *(float4*)(C + (size_t)(m0h + r) * D_MODEL + n0h + c4 * 4) = v;
                }
            }
            __syncthreads();
        }
    }
#endif
}

// Fused QKV GEMM. grid (4,64,3), 288 threads
__global__ void __launch_bounds__(GEMM_THREADS, 1)
gemm_qkv(const __nv_bfloat16* __restrict__ a0, const __nv_bfloat16* __restrict__ a1,
         const __nv_bfloat16* __restrict__ a2,
         const __nv_bfloat16* __restrict__ w0, const __nv_bfloat16* __restrict__ w1,
         const __nv_bfloat16* __restrict__ w2,
         const float* __restrict__ bq, const float* __restrict__ bk,
         const float* __restrict__ bv,
         float* __restrict__ cq, float* __restrict__ ck, float* __restrict__ cv)
{
    extern __shared__ __align__(1024) char smem[];
    const int z = blockIdx.z;
    const __nv_bfloat16* A = (z == 0) ? a0 : (z == 1) ? a1 : a2;
    const __nv_bfloat16* W = (z == 0) ? w0 : (z == 1) ? w1 : w2;
    const float* bias      = (z == 0) ? bq : (z == 1) ? bk : bv;
    float* C               = (z == 0) ? cq : (z == 1) ? ck : cv;
    gemm_core(A, W, bias, C, smem);
}

// Single GEMM (output projection). grid (4,64), 288 threads
__global__ void __launch_bounds__(GEMM_THREADS, 1)
gemm_one(const __nv_bfloat16* __restrict__ A, const __nv_bfloat16* __restrict__ W,
         const float* __restrict__ bias, float* __restrict__ C)
{
    extern __shared__ __align__(1024) char smem[];
    gemm_core(A, W, bias, C, smem);
}

// ---------------------------------------------------------------------------
// Fused split: weights (blocks 0..4095) + activations (blocks 4096..53247)
// fp32 -> [hi|lo] bf16, width 2048. One launch.
// ---------------------------------------------------------------------------
__global__ void __launch_bounds__(256)
split_all(const float* __restrict__ w0, const float* __restrict__ w1,
          const float* __restrict__ w2, const float* __restrict__ w3,
          __nv_bfloat16* __restrict__ o0, __nv_bfloat16* __restrict__ o1,
          __nv_bfloat16* __restrict__ o2, __nv_bfloat16* __restrict__ o3,
          const float* __restrict__ q, const float* __restrict__ k,
          const float* __restrict__ v,
          __nv_bfloat16* __restrict__ oq, __nv_bfloat16* __restrict__ ok,
          __nv_bfloat16* __restrict__ ov)
{
    const int b = blockIdx.x;
    const float* in;
    __nv_bfloat16* out;
    size_t row;
    if (b < 4096) {                       // weights
        const int which = b >> 10;
        row = (size_t)(b & 1023);
        in  = (which == 0) ? w0 : (which == 1) ? w1 : (which == 2) ? w2 : w3;
        out = (which == 0) ? o0 : (which == 1) ? o1 : (which == 2) ? o2 : o3;
    } else {                              // activations
        const int idx = b - 4096;
        const int which = idx >> 14;
        row = (size_t)(idx & 16383);
        in  = (which == 0) ? q : (which == 1) ? k : v;
        out = (which == 0) ? oq : (which == 1) ? ok : ov;
    }

    const int col = threadIdx.x * 4;
    uint2 hi, lo;
    split_row4(*(const float4*)(in + row * D_MODEL + col), hi, lo);
    *(uint2*)(out + row * KA + col)           = hi;
    *(uint2*)(out + row * KA + D_MODEL + col) = lo;
}

// ---------------------------------------------------------------------------
// Per-token "attention" mix; writes X directly as [hi|lo] bf16 split.
// ---------------------------------------------------------------------------
__global__ void __launch_bounds__(256)
attn_mix_split(const float* __restrict__ Q,
               const float* __restrict__ K,
               const float* __restrict__ V,
               const int*   __restrict__ mask,
               __nv_bfloat16* __restrict__ Xs)
{
    __shared__ __align__(16) float qs[D_MODEL];
    __shared__ __align__(16) float vs[D_MODEL];
    __shared__ __align__(16) float kT[D_MODEL];
    __shared__ float a_s[NUM_HEADS * NUM_HEADS];

    const int t = threadIdx.x;
    const size_t base = (size_t)blockIdx.x * D_MODEL;

    float4 q4 = *(const float4*)(Q + base + t * 4);
    float4 v4 = *(const float4*)(V + base + t * 4);
    float4 k4 = *(const float4*)(K + base + t * 4);
    *(float4*)(qs + t * 4) = q4;
    *(float4*)(vs + t * 4) = v4;
    {   // vectorized swizzled transpose: 4 consecutive d share l and d>>2
        int j = t * 4;
        int d0 = j & 63, l0 = j >> 6;
        int x = l0 ^ (d0 >> 2);
        *(float4*)(kT + (d0 >> 2) * 64 + x * 4) = k4;
    }
    __syncthreads();

    const int i = t >> 4, l = t & 15;
    float e = 0.0f;
#pragma unroll
    for (int d = 0; d < HEAD_DIM; d += 4) {
        float4 qv = *(const float4*)(qs + i * 64 + d);
        float4 kv = *(const float4*)(kT + (d >> 2) * 64 + (l ^ (d >> 2)) * 4);
        e += qv.x * kv.x + qv.y * kv.y + qv.z * kv.z + qv.w * kv.w;
    }

    const int mk = mask[blockIdx.x];
    e = mk ? e * 0.03125f : 0.0f;         // 1/sqrt(1024); masked -> uniform

    float mx = e;
#pragma unroll
    for (int off = 8; off; off >>= 1)
        mx = fmaxf(mx, __shfl_xor_sync(0xffffffffu, mx, off, 16));
    float p = expf(e - mx);
    float s = p;
#pragma unroll
    for (int off = 8; off; off >>= 1)
        s += __shfl_xor_sync(0xffffffffu, s, off, 16);
    a_s[t] = p / s;
    __syncthreads();

    const int od = t & 63;
    const int oib = t >> 6;
    float acc0 = 0.f, acc1 = 0.f, acc2 = 0.f, acc3 = 0.f;
#pragma unroll
    for (int ll = 0; ll < 16; ll++) {
        float vv = vs[ll * 64 + od];
        acc0 += a_s[(0 * 4 + oib) * 16 + ll] * vv;
        acc1 += a_s[(1 * 4 + oib) * 16 + ll] * vv;
        acc2 += a_s[(2 * 4 + oib) * 16 + ll] * vv;
        acc3 += a_s[(3 * 4 + oib) * 16 + ll] * vv;
    }
    const size_t obase = (size_t)blockIdx.x * KA;
    float accs[4] = {acc0, acc1, acc2, acc3};
#pragma unroll
    for (int r = 0; r < 4; r++) {
        int o = r * 256 + t;
        __nv_bfloat16 h  = __float2bfloat16(accs[r]);
        __nv_bfloat16 lo = __float2bfloat16(accs[r] - __bfloat162float(h));
        Xs[obase + o]           = h;
        Xs[obase + D_MODEL + o] = lo;
    }
}

// ---------------------------------------------------------------------------
// Launch
// ---------------------------------------------------------------------------
extern "C" void kernel_launch(void* const* d_in, const int* in_sizes, int n_in,
                              void* d_out, int out_size)
{
    (void)in_sizes; (void)n_in; (void)out_size;
    const float* query = (const float*)d_in[0];
    const float* key   = (const float*)d_in[1];
    const float* value = (const float*)d_in[2];
    const int*   mask  = (const int*)  d_in[3];
    const float* Wq = (const float*)d_in[4];
    const float* bq = (const float*)d_in[5];
    const float* Wk = (const float*)d_in[6];
    const float* bk = (const float*)d_in[7];
    const float* Wv = (const float*)d_in[8];
    const float* bv = (const float*)d_in[9];
    const float* Wo = (const float*)d_in[10];
    const float* bo = (const float*)d_in[11];
    float* out = (float*)d_out;

    void *pQ, *pK, *pV, *pA0, *pA1, *pA2, *pW0, *pW1, *pW2, *pW3;
    cudaGetSymbolAddress(&pQ, g_Q);
    cudaGetSymbolAddress(&pK, g_K);
    cudaGetSymbolAddress(&pV, g_V);
    cudaGetSymbolAddress(&pA0, g_a0);
    cudaGetSymbolAddress(&pA1, g_a1);
    cudaGetSymbolAddress(&pA2, g_a2);
    cudaGetSymbolAddress(&pW0, g_w0);
    cudaGetSymbolAddress(&pW1, g_w1);
    cudaGetSymbolAddress(&pW2, g_w2);
    cudaGetSymbolAddress(&pW3, g_w3);

    cudaFuncSetAttribute(gemm_qkv,
                         cudaFuncAttributeMaxDynamicSharedMemorySize, SMEM_TOTAL);
    cudaFuncSetAttribute(gemm_one,
                         cudaFuncAttributeMaxDynamicSharedMemorySize, SMEM_TOTAL);

    split_all<<<4096 + 3 * M_TOK, 256>>>(
        Wq, Wk, Wv, Wo,
        (__nv_bfloat16*)pW0, (__nv_bfloat16*)pW1,
        (__nv_bfloat16*)pW2, (__nv_bfloat16*)pW3,
        query, key, value,
        (__nv_bfloat16*)pA0, (__nv_bfloat16*)pA1, (__nv_bfloat16*)pA2);

    dim3 qkvgrid(D_MODEL / BN, M_TOK / BMC, 3);   // (4, 64, 3)
    gemm_qkv<<<qkvgrid, GEMM_THREADS, SMEM_TOTAL>>>(
        (__nv_bfloat16*)pA0, (__nv_bfloat16*)pA1, (__nv_bfloat16*)pA2,
        (__nv_bfloat16*)pW0, (__nv_bfloat16*)pW1, (__nv_bfloat16*)pW2,
        bq, bk, bv, (float*)pQ, (float*)pK, (float*)pV);

    attn_mix_split<<<M_TOK, 256>>>((const float*)pQ, (const float*)pK,
                                   (const float*)pV, mask, (__nv_bfloat16*)pA0);

    dim3 ogrid(D_MODEL / BN, M_TOK / BMC);        // (4, 64)
    gemm_one<<<ogrid, GEMM_THREADS, SMEM_TOTAL>>>((__nv_bfloat16*)pA0,
                                                  (__nv_bfloat16*)pW3, bo, out);
}